// round 12
// baseline (speedup 1.0000x reference)
#include <cuda_runtime.h>
#include <math.h>

#define CL   1024
#define CB   8
#define CD   512
#define CH   8
#define CHD  64
#define CLT  32
#define TOK  (CL*CB)          // 8192
#define SUMLK 2081            // 1536+384+107+54
#define KEYTOK (SUMLK*CB)     // 16648

// ---------------- static scratch (allocation-free rule) ----------------
__device__ float g_sent[CB*CD];
__device__ float g_scores[CB*CL];
__device__ int   g_vm[CB*CL];
__device__ int   g_tm[CB*CLT];
__device__ int   g_ecm[CB*CL];
__device__ int   g_km[CB*SUMLK];
__device__ float g_keys[(size_t)KEYTOK*CD];
__device__ float g_qkv[(size_t)TOK*3*CD];      // EC QKV
__device__ float g_kv[(size_t)KEYTOK*2*CD];    // CC KV
__device__ float g_q4[(size_t)4*TOK*CD];
__device__ float g_a4[(size_t)4*TOK*CD];
__device__ float g_attnO[(size_t)TOK*CD];
__device__ float g_t0[(size_t)TOK*CD];
__device__ float g_xec[(size_t)TOK*CD];
__device__ float g_xcc[(size_t)TOK*CD];
__device__ float g_hid[(size_t)TOK*4*CD];
__device__ float g_out2[(size_t)TOK*CD];

__constant__ int cc_Lk[4]  = {1536, 384, 107, 54};
__constant__ int cc_Off[4] = {0, 12288, 15360, 16216};
// pooled-segment tables (8 pools flattened over 2081 positions)
__constant__ int pp_s[8]     = {1, 2, 4, 8, 16, 24, 32, 48};
__constant__ int pp_start[8] = {0, 1024, 1536, 1792, 1920, 1984, 2027, 2059};
__constant__ int pp_coff[8]  = {0, 1024, 0, 256, 0, 64, 0, 32};
__constant__ int pp_grp[8]   = {0, 0, 1, 1, 2, 2, 3, 3};

// ---------------- tf32 helpers ----------------
__device__ __forceinline__ unsigned f2tf32(float x) {
    unsigned r; asm("cvt.rna.tf32.f32 %0, %1;" : "=r"(r) : "f"(x)); return r;
}
__device__ __forceinline__ void mma_tf32(float* d, const unsigned* a, const unsigned* b) {
    asm volatile(
        "mma.sync.aligned.m16n8k8.row.col.f32.tf32.tf32.f32 "
        "{%0,%1,%2,%3}, {%4,%5,%6,%7}, {%8,%9}, {%0,%1,%2,%3};\n"
        : "+f"(d[0]), "+f"(d[1]), "+f"(d[2]), "+f"(d[3])
        : "r"(a[0]), "r"(a[1]), "r"(a[2]), "r"(a[3]),
          "r"(b[0]), "r"(b[1]));
}

// ---------------- mask canonicalization ----------------
__global__ void canon_mask(const void* __restrict__ src, int n, int* __restrict__ dst) {
    unsigned int w = *(const unsigned int*)src;
    int mode = (w == 1u) ? 0 : (w == 0x01010101u) ? 1 : 2;
    for (int i = blockIdx.x * blockDim.x + threadIdx.x; i < n; i += gridDim.x * blockDim.x) {
        int v;
        if (mode == 0)      v = ((const int*)src)[i] != 0;
        else if (mode == 1) v = ((const unsigned char*)src)[i] != 0;
        else                v = ((const float*)src)[i] != 0.f;
        dst[i] = v;
    }
}

// ---------------- sentence-level text pooling ----------------
__global__ void sent_pool(const float* __restrict__ txt, const int* __restrict__ tm,
                          const float* __restrict__ wts_w, const float* __restrict__ wts_b,
                          float* __restrict__ sent) {
    int b = blockIdx.x;
    __shared__ float aw[CLT];
    int tid = threadIdx.x, wid = tid >> 5, lane = tid & 31;
    for (int t = wid; t < CLT; t += 8) {
        const float* row = txt + ((size_t)t * CB + b) * CD;
        float s = 0.f;
        for (int d = lane; d < CD; d += 32) s += row[d] * wts_w[d];
        #pragma unroll
        for (int o = 16; o; o >>= 1) s += __shfl_xor_sync(~0u, s, o);
        if (lane == 0) aw[t] = tm[b * CLT + t] ? s + wts_b[0] : -1e9f;
    }
    __syncthreads();
    if (tid == 0) {
        float mx = -3.4e38f;
        for (int t = 0; t < CLT; t++) mx = fmaxf(mx, aw[t]);
        float sm = 0.f;
        for (int t = 0; t < CLT; t++) { aw[t] = expf(aw[t] - mx); sm += aw[t]; }
        float inv = 1.f / sm;
        for (int t = 0; t < CLT; t++) aw[t] *= inv;
    }
    __syncthreads();
    for (int d = tid; d < CD; d += blockDim.x) {
        float s = 0.f;
        for (int t = 0; t < CLT; t++) s += aw[t] * txt[((size_t)t * CB + b) * CD + d];
        sent[b * CD + d] = s;
    }
}

// ---------------- relevance scores ----------------
__global__ void score_dot(const float* __restrict__ x, const float* __restrict__ sent,
                          const int* __restrict__ vm, float* __restrict__ scores) {
    int w = (blockIdx.x * blockDim.x + threadIdx.x) >> 5;
    int lane = threadIdx.x & 31;
    if (w >= CB * CL) return;
    int b = w & 7, l = w >> 3;
    const float4* xr = (const float4*)(x + ((size_t)(l * CB + b)) * CD);
    const float4* sb = (const float4*)(sent + b * CD);
    float acc = 0.f;
    for (int d = lane; d < CD / 4; d += 32) {
        float4 a = xr[d], c = sb[d];
        acc += a.x * c.x + a.y * c.y + a.z * c.z + a.w * c.w;
    }
    #pragma unroll
    for (int o = 16; o; o >>= 1) acc += __shfl_xor_sync(~0u, acc, o);
    if (lane == 0) {
        if (!vm[b * CL + l]) acc = -1e9f;
        scores[b * CL + l] = acc;
    }
}

// ---------------- exact rank top-k ----------------
__global__ void rank_topk(const float* __restrict__ scores, const int* __restrict__ vm,
                          int* __restrict__ ecm) {
    int b = blockIdx.x, l = threadIdx.x;
    __shared__ float s[CL];
    float mine = scores[b * CL + l];
    s[l] = mine;
    __syncthreads();
    int cnt = 0;
    for (int j = 0; j < CL; j++) {
        float sj = s[j];
        cnt += (sj > mine) || (sj == mine && j < l);
    }
    ecm[b * CL + l] = (cnt >= CL / 2) || !vm[b * CL + l];
}

// ======== tf32 TC GEMM (R8 form): static smem, reg-prefetch, tf32 in smem ========
// mode 0: C[z] = A[z](MxK) @ W[z](NxK)^T + bias[z], strides aZ/wZ/bZ/cZ.
// mode 1 (CC KV): per-z ragged M = cc_Lk[z]*CB, A/C offset by cc_Off[z] rows.
// Ab2: optional second A operand summed element-wise before tf32 conversion.
__global__ void gemm_tc(const float* __restrict__ Ab, const float* __restrict__ Ab2,
                        size_t aZ,
                        const float* __restrict__ Wb, size_t wZ,
                        const float* __restrict__ biasb, size_t bZ,
                        float* __restrict__ Cb, size_t cZ,
                        int M, int N, int K, int relu, int kvmode) {
    __shared__ unsigned As[128][36];   // tf32 bit patterns
    __shared__ unsigned Ws[128][36];
    int z = blockIdx.z;
    const float* A;
    const float* W = Wb + (size_t)z * wZ;
    const float* bias = biasb + (size_t)z * bZ;
    float* C;
    if (kvmode) {
        M = cc_Lk[z] * CB;
        A = Ab + (size_t)cc_Off[z] * CD;
        C = Cb + (size_t)cc_Off[z] * 2 * CD;
    } else {
        A = Ab + (size_t)z * aZ;
        C = Cb + (size_t)z * cZ;
    }

    int row0 = blockIdx.y << 7, col0 = blockIdx.x << 7;
    if (row0 >= M) return;

    int tid = threadIdx.x;
    int wid = tid >> 5, lane = tid & 31;
    int g = lane >> 2, tg = lane & 3;
    int wm = wid >> 2, wn = wid & 3;
    int mb = wm * 64, nb = wn * 32;
    float acc[4][4][4] = {};
    float4 pa[4], pw[4];

    // prefetch chunk 0
    #pragma unroll
    for (int v = 0; v < 4; v++) {
        int idx = tid + v * 256;
        int r = idx >> 3, c4 = idx & 7;
        int gm = row0 + r;
        pa[v] = make_float4(0.f, 0.f, 0.f, 0.f);
        if (gm < M) {
            pa[v] = *(const float4*)&A[(size_t)gm * K + c4 * 4];
            if (Ab2) {
                float4 e = *(const float4*)&Ab2[(size_t)gm * K + c4 * 4];
                pa[v].x += e.x; pa[v].y += e.y; pa[v].z += e.z; pa[v].w += e.w;
            }
        }
        pw[v] = *(const float4*)&W[(size_t)(col0 + r) * K + c4 * 4];
    }

    for (int k0 = 0; k0 < K; k0 += 32) {
        #pragma unroll
        for (int v = 0; v < 4; v++) {
            int idx = tid + v * 256;
            int r = idx >> 3, c4 = idx & 7;
            As[r][c4 * 4 + 0] = f2tf32(pa[v].x); As[r][c4 * 4 + 1] = f2tf32(pa[v].y);
            As[r][c4 * 4 + 2] = f2tf32(pa[v].z); As[r][c4 * 4 + 3] = f2tf32(pa[v].w);
            Ws[r][c4 * 4 + 0] = f2tf32(pw[v].x); Ws[r][c4 * 4 + 1] = f2tf32(pw[v].y);
            Ws[r][c4 * 4 + 2] = f2tf32(pw[v].z); Ws[r][c4 * 4 + 3] = f2tf32(pw[v].w);
        }
        __syncthreads();
        if (k0 + 32 < K) {
            int kn = k0 + 32;
            #pragma unroll
            for (int v = 0; v < 4; v++) {
                int idx = tid + v * 256;
                int r = idx >> 3, c4 = idx & 7;
                int gm = row0 + r;
                pa[v] = make_float4(0.f, 0.f, 0.f, 0.f);
                if (gm < M) {
                    pa[v] = *(const float4*)&A[(size_t)gm * K + kn + c4 * 4];
                    if (Ab2) {
                        float4 e = *(const float4*)&Ab2[(size_t)gm * K + kn + c4 * 4];
                        pa[v].x += e.x; pa[v].y += e.y; pa[v].z += e.z; pa[v].w += e.w;
                    }
                }
                pw[v] = *(const float4*)&W[(size_t)(col0 + r) * K + kn + c4 * 4];
            }
        }
        #pragma unroll
        for (int kk = 0; kk < 32; kk += 8) {
            unsigned af[4][4], bf[4][2];
            #pragma unroll
            for (int i = 0; i < 4; i++) {
                int m = mb + i * 16;
                af[i][0] = As[m + g][kk + tg];
                af[i][1] = As[m + g + 8][kk + tg];
                af[i][2] = As[m + g][kk + tg + 4];
                af[i][3] = As[m + g + 8][kk + tg + 4];
            }
            #pragma unroll
            for (int j = 0; j < 4; j++) {
                int n = nb + j * 8;
                bf[j][0] = Ws[n + g][kk + tg];
                bf[j][1] = Ws[n + g][kk + tg + 4];
            }
            #pragma unroll
            for (int i = 0; i < 4; i++)
                #pragma unroll
                for (int j = 0; j < 4; j++) mma_tf32(acc[i][j], af[i], bf[j]);
        }
        __syncthreads();
    }
    #pragma unroll
    for (int i = 0; i < 4; i++) {
        #pragma unroll
        for (int j = 0; j < 4; j++) {
            int gn = col0 + nb + j * 8 + tg * 2;
            float b0 = bias[gn], b1 = bias[gn + 1];
            #pragma unroll
            for (int h = 0; h < 2; h++) {
                int gm = row0 + mb + i * 16 + g + h * 8;
                if (gm >= M) continue;
                float c0 = acc[i][j][h * 2 + 0] + b0;
                float c1 = acc[i][j][h * 2 + 1] + b1;
                if (relu) { c0 = fmaxf(c0, 0.f); c1 = fmaxf(c1, 0.f); }
                *(float2*)&C[(size_t)gm * N + gn] = make_float2(c0, c1);
            }
        }
    }
}

// ================= fused flash attention =================
#define FA_QS   0
#define FA_KS   (128*68)
#define FA_VS   (FA_KS + 64*68)
#define FA_PS   (FA_VS + 64*68)
#define FA_KM   (FA_PS + 8*16*68)
#define FA_SMEM ((FA_KM + 64) * 4)

__global__ void __launch_bounds__(256, 2)
flash_attn(const float* __restrict__ Qb, int sQ, int qoff, size_t qZ,
           const float* __restrict__ KVb, int sKV, int koff, int voff,
           const int* __restrict__ ignb, float* __restrict__ Ob, size_t oZ,
           int Lk0, float scale, int multi) {
    extern __shared__ unsigned sm[];
    unsigned* Qs = sm + FA_QS;
    unsigned* Ks = sm + FA_KS;
    unsigned* Vs = sm + FA_VS;
    unsigned* Ps = sm + FA_PS;
    int* kms = (int*)(sm + FA_KM);

    int z = blockIdx.z;
    int Lk = Lk0, rowoff = 0;
    const float* Q = Qb;
    const int* ign = ignb;
    float* O = Ob;
    if (multi) {
        Lk = cc_Lk[z];
        rowoff = cc_Off[z];
        Q = Qb + (size_t)z * qZ;
        O = Ob + (size_t)z * oZ;
        ign = ignb + rowoff;
    }

    int bh = blockIdx.y, b = bh >> 3, h = bh & 7;
    int lq0 = blockIdx.x << 7;
    int tid = threadIdx.x, wid = tid >> 5, lane = tid & 31;
    int g = lane >> 2, tg = lane & 3;
    unsigned* wp = Ps + wid * (16 * 68);
    int mb = wid * 16;

    #pragma unroll
    for (int v = 0; v < 8; v++) {
        int idx = tid + v * 256;
        int r = idx >> 4, c4 = idx & 15;
        float4 q = *(const float4*)&Q[((size_t)((lq0 + r) * CB + b)) * sQ + qoff + h * CHD + c4 * 4];
        Qs[r * 68 + c4 * 4 + 0] = f2tf32(q.x);
        Qs[r * 68 + c4 * 4 + 1] = f2tf32(q.y);
        Qs[r * 68 + c4 * 4 + 2] = f2tf32(q.z);
        Qs[r * 68 + c4 * 4 + 3] = f2tf32(q.w);
    }

    float o[8][4] = {};
    float mA = -1e30f, mB = -1e30f, lA = 0.f, lB = 0.f;

    for (int kt = 0; kt < Lk; kt += 64) {
        __syncthreads();
        #pragma unroll
        for (int v = 0; v < 4; v++) {
            int idx = tid + v * 256;
            int r = idx >> 4, c4 = idx & 15;
            int key = kt + r;
            float4 kv = make_float4(0.f, 0.f, 0.f, 0.f);
            float4 vv = make_float4(0.f, 0.f, 0.f, 0.f);
            if (key < Lk) {
                size_t base = ((size_t)(rowoff + key * CB + b)) * sKV;
                kv = *(const float4*)&KVb[base + koff + h * CHD + c4 * 4];
                vv = *(const float4*)&KVb[base + voff + h * CHD + c4 * 4];
            }
            Ks[r * 68 + c4 * 4 + 0] = f2tf32(kv.x);
            Ks[r * 68 + c4 * 4 + 1] = f2tf32(kv.y);
            Ks[r * 68 + c4 * 4 + 2] = f2tf32(kv.z);
            Ks[r * 68 + c4 * 4 + 3] = f2tf32(kv.w);
            Vs[r * 68 + c4 * 4 + 0] = f2tf32(vv.x);
            Vs[r * 68 + c4 * 4 + 1] = f2tf32(vv.y);
            Vs[r * 68 + c4 * 4 + 2] = f2tf32(vv.z);
            Vs[r * 68 + c4 * 4 + 3] = f2tf32(vv.w);
        }
        if (tid < 64) {
            int key = kt + tid;
            kms[tid] = (key < Lk) ? ign[b * Lk + key] : 1;
        }
        __syncthreads();

        float s[8][4] = {};
        #pragma unroll
        for (int kk = 0; kk < 64; kk += 8) {
            unsigned a[4];
            a[0] = Qs[(mb + g) * 68 + kk + tg];
            a[1] = Qs[(mb + g + 8) * 68 + kk + tg];
            a[2] = Qs[(mb + g) * 68 + kk + tg + 4];
            a[3] = Qs[(mb + g + 8) * 68 + kk + tg + 4];
            #pragma unroll
            for (int j = 0; j < 8; j++) {
                unsigned bfr[2];
                bfr[0] = Ks[(j * 8 + g) * 68 + kk + tg];
                bfr[1] = Ks[(j * 8 + g) * 68 + kk + tg + 4];
                mma_tf32(s[j], a, bfr);
            }
        }
        #pragma unroll
        for (int j = 0; j < 8; j++) {
            int c0 = j * 8 + tg * 2;
            int m0 = kms[c0], m1 = kms[c0 + 1];
            s[j][0] = m0 ? -1e30f : s[j][0] * scale;
            s[j][1] = m1 ? -1e30f : s[j][1] * scale;
            s[j][2] = m0 ? -1e30f : s[j][2] * scale;
            s[j][3] = m1 ? -1e30f : s[j][3] * scale;
        }
        float tA = -3.4e38f, tB = -3.4e38f;
        #pragma unroll
        for (int j = 0; j < 8; j++) {
            tA = fmaxf(tA, fmaxf(s[j][0], s[j][1]));
            tB = fmaxf(tB, fmaxf(s[j][2], s[j][3]));
        }
        #pragma unroll
        for (int off = 1; off <= 2; off <<= 1) {
            tA = fmaxf(tA, __shfl_xor_sync(~0u, tA, off));
            tB = fmaxf(tB, __shfl_xor_sync(~0u, tB, off));
        }
        float mnA = fmaxf(mA, tA), mnB = fmaxf(mB, tB);
        float aA = __expf(mA - mnA), aB = __expf(mB - mnB);
        float suA = 0.f, suB = 0.f;
        #pragma unroll
        for (int j = 0; j < 8; j++) {
            s[j][0] = __expf(s[j][0] - mnA);
            s[j][1] = __expf(s[j][1] - mnA);
            s[j][2] = __expf(s[j][2] - mnB);
            s[j][3] = __expf(s[j][3] - mnB);
            suA += s[j][0] + s[j][1];
            suB += s[j][2] + s[j][3];
        }
        #pragma unroll
        for (int off = 1; off <= 2; off <<= 1) {
            suA += __shfl_xor_sync(~0u, suA, off);
            suB += __shfl_xor_sync(~0u, suB, off);
        }
        lA = lA * aA + suA;  mA = mnA;
        lB = lB * aB + suB;  mB = mnB;
        #pragma unroll
        for (int j = 0; j < 8; j++) {
            o[j][0] *= aA; o[j][1] *= aA;
            o[j][2] *= aB; o[j][3] *= aB;
        }
        #pragma unroll
        for (int j = 0; j < 8; j++) {
            int c0 = j * 8 + tg * 2;
            wp[g * 68 + c0]           = f2tf32(s[j][0]);
            wp[g * 68 + c0 + 1]       = f2tf32(s[j][1]);
            wp[(g + 8) * 68 + c0]     = f2tf32(s[j][2]);
            wp[(g + 8) * 68 + c0 + 1] = f2tf32(s[j][3]);
        }
        __syncwarp();
        #pragma unroll
        for (int kk = 0; kk < 64; kk += 8) {
            unsigned a[4];
            a[0] = wp[g * 68 + kk + tg];
            a[1] = wp[(g + 8) * 68 + kk + tg];
            a[2] = wp[g * 68 + kk + tg + 4];
            a[3] = wp[(g + 8) * 68 + kk + tg + 4];
            #pragma unroll
            for (int j = 0; j < 8; j++) {
                unsigned bfr[2];
                bfr[0] = Vs[(kk + tg) * 68 + j * 8 + g];
                bfr[1] = Vs[(kk + tg + 4) * 68 + j * 8 + g];
                mma_tf32(o[j], a, bfr);
            }
        }
        __syncwarp();
    }
    float iA = 1.f / lA, iB = 1.f / lB;
    int lqA = lq0 + mb + g, lqB = lqA + 8;
    #pragma unroll
    for (int j = 0; j < 8; j++) {
        int c = h * CHD + j * 8 + tg * 2;
        *(float2*)&O[((size_t)(lqA * CB + b)) * CD + c] = make_float2(o[j][0] * iA, o[j][1] * iA);
        *(float2*)&O[((size_t)(lqB * CB + b)) * CD + c] = make_float2(o[j][2] * iB, o[j][3] * iB);
    }
}

// ---------------- all pools in one launch (flattened 2081 positions) ----------------
__global__ void pool_all(const float* __restrict__ x, const int* __restrict__ vm,
                         float* __restrict__ keys, int* __restrict__ kmask) {
    int q = blockIdx.x, b = blockIdx.y;
    int tid = threadIdx.x;
    int p = 7;
    #pragma unroll
    for (int i = 7; i >= 1; i--) if (q < pp_start[i]) p = i - 1;
    int lp = q - pp_start[p];
    int s = pp_s[p];
    int gidx = pp_grp[p];
    int orowIdx = cc_Off[gidx] + (pp_coff[p] + lp) * CB + b;
    size_t orow = (size_t)orowIdx * CD;
    for (int d = tid; d < CD; d += 256) {
        float m = -3.4e38f;
        for (int j = 0; j < s; j++) {
            int l = lp * s + j;
            float v = (l < CL) ? x[((size_t)l * CB + b) * CD + d] : 0.f;
            m = fmaxf(m, v);
        }
        keys[orow + d] = m;
    }
    if (tid == 0) {
        int any = 0;
        for (int j = 0; j < s; j++) {
            int l = lp * s + j;
            if (l < CL && vm[b * CL + l]) any = 1;
        }
        int Lkg = cc_Lk[gidx];
        kmask[cc_Off[gidx] + b * Lkg + (pp_coff[p] + lp)] = !any;
    }
}

// ---------------- LayerNorm(A + R) ----------------
__global__ void ln_res(const float* __restrict__ A, const float* __restrict__ R,
                       const float* __restrict__ g, const float* __restrict__ be,
                       float* __restrict__ out) {
    size_t row = blockIdx.x;
    int tid = threadIdx.x;
    __shared__ float red[256];
    float v0 = A[row * CD + tid]       + R[row * CD + tid];
    float v1 = A[row * CD + tid + 256] + R[row * CD + tid + 256];
    red[tid] = v0 + v1; __syncthreads();
    for (int s = 128; s > 0; s >>= 1) { if (tid < s) red[tid] += red[tid + s]; __syncthreads(); }
    float mu = red[0] / CD; __syncthreads();
    float d0 = v0 - mu, d1 = v1 - mu;
    red[tid] = d0 * d0 + d1 * d1; __syncthreads();
    for (int s = 128; s > 0; s >>= 1) { if (tid < s) red[tid] += red[tid + s]; __syncthreads(); }
    float rstd = rsqrtf(red[0] / CD + 1e-5f);
    out[row * CD + tid]       = d0 * rstd * g[tid]       + be[tid];
    out[row * CD + tid + 256] = d1 * rstd * g[tid + 256] + be[tid + 256];
}

// ---------------- LayerNorm((X1+X2) + R)  — fused add2 + ln ----------------
__global__ void ln_res3(const float* __restrict__ X1, const float* __restrict__ X2,
                        const float* __restrict__ R,
                        const float* __restrict__ g, const float* __restrict__ be,
                        float* __restrict__ out) {
    size_t row = blockIdx.x;
    int tid = threadIdx.x;
    __shared__ float red[256];
    size_t i0 = row * CD + tid, i1 = i0 + 256;
    float v0 = (X1[i0] + X2[i0]) + R[i0];
    float v1 = (X1[i1] + X2[i1]) + R[i1];
    red[tid] = v0 + v1; __syncthreads();
    for (int s = 128; s > 0; s >>= 1) { if (tid < s) red[tid] += red[tid + s]; __syncthreads(); }
    float mu = red[0] / CD; __syncthreads();
    float d0 = v0 - mu, d1 = v1 - mu;
    red[tid] = d0 * d0 + d1 * d1; __syncthreads();
    for (int s = 128; s > 0; s >>= 1) { if (tid < s) red[tid] += red[tid + s]; __syncthreads(); }
    float rstd = rsqrtf(red[0] / CD + 1e-5f);
    out[i0] = d0 * rstd * g[tid]       + be[tid];
    out[i1] = d1 * rstd * g[tid + 256] + be[tid + 256];
}

// ---------------- LayerNorm(x + P0+P1+P2+P3) ----------------
__global__ void ln_res4(const float* __restrict__ X, const float* __restrict__ P, size_t pZ,
                        const float* __restrict__ g, const float* __restrict__ be,
                        float* __restrict__ out) {
    size_t row = blockIdx.x;
    int tid = threadIdx.x;
    __shared__ float red[256];
    size_t i0 = row * CD + tid, i1 = i0 + 256;
    float v0 = X[i0] + P[i0] + P[i0 + pZ] + P[i0 + 2 * pZ] + P[i0 + 3 * pZ];
    float v1 = X[i1] + P[i1] + P[i1 + pZ] + P[i1 + 2 * pZ] + P[i1 + 3 * pZ];
    red[tid] = v0 + v1; __syncthreads();
    for (int s = 128; s > 0; s >>= 1) { if (tid < s) red[tid] += red[tid + s]; __syncthreads(); }
    float mu = red[0] / CD; __syncthreads();
    float d0 = v0 - mu, d1 = v1 - mu;
    red[tid] = d0 * d0 + d1 * d1; __syncthreads();
    for (int s = 128; s > 0; s >>= 1) { if (tid < s) red[tid] += red[tid + s]; __syncthreads(); }
    float rstd = rsqrtf(red[0] / CD + 1e-5f);
    out[i0] = d0 * rstd * g[tid]       + be[tid];
    out[i1] = d1 * rstd * g[tid + 256] + be[tid + 256];
}

// ---------------- launch ----------------
static inline int cdiv(int a, int b) { return (a + b - 1) / b; }

extern "C" void kernel_launch(void* const* d_in, const int* in_sizes, int n_in,
                              void* d_out, int out_size) {
    const float* x        = (const float*)d_in[0];
    const float* txt      = (const float*)d_in[1];
    const void*  vmask    = d_in[2];
    const void*  tmask    = d_in[3];
    const float* wts_w    = (const float*)d_in[4];
    const float* wts_b    = (const float*)d_in[5];
    const float* ec_in_w  = (const float*)d_in[6];
    const float* ec_in_b  = (const float*)d_in[7];
    const float* ec_out_w = (const float*)d_in[8];
    const float* ec_out_b = (const float*)d_in[9];
    const float* cc_in_w  = (const float*)d_in[10];
    const float* cc_in_b  = (const float*)d_in[11];
    const float* cc_out_w = (const float*)d_in[12];
    const float* cc_out_b = (const float*)d_in[13];
    const float* ec_g     = (const float*)d_in[14];
    const float* ec_b     = (const float*)d_in[15];
    const float* cc_g     = (const float*)d_in[16];
    const float* cc_b     = (const float*)d_in[17];
    const float* fu_g     = (const float*)d_in[18];
    const float* fu_b     = (const float*)d_in[19];
    const float* lin1_w   = (const float*)d_in[20];
    const float* lin1_b   = (const float*)d_in[21];
    const float* lin2_w   = (const float*)d_in[22];
    const float* lin2_b   = (const float*)d_in[23];
    float* out = (float*)d_out;

    static int init_done = 0;
    static cudaStream_t s1, s2;
    static cudaEvent_t evFork, evVm, evB, evTopk;
    if (!init_done) {
        cudaFuncSetAttribute(flash_attn, cudaFuncAttributeMaxDynamicSharedMemorySize, FA_SMEM);
        cudaStreamCreateWithFlags(&s1, cudaStreamNonBlocking);
        cudaStreamCreateWithFlags(&s2, cudaStreamNonBlocking);
        cudaEventCreateWithFlags(&evFork, cudaEventDisableTiming);
        cudaEventCreateWithFlags(&evVm,   cudaEventDisableTiming);
        cudaEventCreateWithFlags(&evB,    cudaEventDisableTiming);
        cudaEventCreateWithFlags(&evTopk, cudaEventDisableTiming);
        init_done = 1;
    }

    float *sent, *scores, *keys, *qkv, *kv, *q4, *a4, *aO, *t0, *xec, *xcc, *hid, *out2;
    int *vm, *tm, *ecm, *km;
    cudaGetSymbolAddress((void**)&sent,   g_sent);
    cudaGetSymbolAddress((void**)&scores, g_scores);
    cudaGetSymbolAddress((void**)&vm,     g_vm);
    cudaGetSymbolAddress((void**)&tm,     g_tm);
    cudaGetSymbolAddress((void**)&ecm,    g_ecm);
    cudaGetSymbolAddress((void**)&km,     g_km);
    cudaGetSymbolAddress((void**)&keys,   g_keys);
    cudaGetSymbolAddress((void**)&qkv,    g_qkv);
    cudaGetSymbolAddress((void**)&kv,     g_kv);
    cudaGetSymbolAddress((void**)&q4,     g_q4);
    cudaGetSymbolAddress((void**)&a4,     g_a4);
    cudaGetSymbolAddress((void**)&aO,     g_attnO);
    cudaGetSymbolAddress((void**)&t0,     g_t0);
    cudaGetSymbolAddress((void**)&xec,    g_xec);
    cudaGetSymbolAddress((void**)&xcc,    g_xcc);
    cudaGetSymbolAddress((void**)&hid,    g_hid);
    cudaGetSymbolAddress((void**)&out2,   g_out2);

    const float scale = 0.125f;   // 1/sqrt(64)
    const size_t TD = (size_t)TOK * CD;

    // ---- fork ----
    cudaEventRecord(evFork, 0);
    cudaStreamWaitEvent(s1, evFork, 0);
    cudaStreamWaitEvent(s2, evFork, 0);

    // ---- stream 0: vm + EC gemms/flash ----
    canon_mask<<<32, 256>>>(vmask, CB * CL, vm);
    cudaEventRecord(evVm, 0);
    gemm_tc<<<dim3(12, 64), 256>>>(x, (const float*)0, 0, ec_in_w, 0, ec_in_b, 0, qkv, 0,
                                   TOK, 3 * CD, CD, 0, 0);

    // ---- stream s2: topk chain (overlaps with QKV gemm) ----
    canon_mask<<<1, 256, 0, s2>>>(tmask, CB * CLT, tm);
    sent_pool<<<CB, 256, 0, s2>>>(txt, tm, wts_w, wts_b, sent);
    cudaStreamWaitEvent(s2, evVm, 0);
    score_dot<<<1024, 256, 0, s2>>>(x, sent, vm, scores);
    rank_topk<<<CB, 1024, 0, s2>>>(scores, vm, ecm);
    cudaEventRecord(evTopk, s2);

    cudaStreamWaitEvent(0, evTopk, 0);
    flash_attn<<<dim3(8, 64, 1), 256, FA_SMEM>>>(qkv, 3 * CD, 0, 0, qkv, 3 * CD, CD, 2 * CD,
                                                 ecm, aO, 0, CL, scale, 0);
    gemm_tc<<<dim3(4, 64), 256>>>(aO, (const float*)0, 0, ec_out_w, 0, ec_out_b, 0, t0, 0,
                                  TOK, CD, CD, 0, 0);
    ln_res<<<TOK, 256>>>(x, t0, ec_g, ec_b, xec);

    // ---- stream s1: CC branch ----
    gemm_tc<<<dim3(4, 64, 4), 256, 0, s1>>>(x, (const float*)0, 0,
                                            cc_in_w, (size_t)3 * CD * CD,
                                            cc_in_b, (size_t)3 * CD,
                                            q4, TD, TOK, CD, CD, 0, 0);
    cudaStreamWaitEvent(s1, evVm, 0);
    pool_all<<<dim3(SUMLK, CB), 256, 0, s1>>>(x, vm, keys, km);
    gemm_tc<<<dim3(8, 96, 4), 256, 0, s1>>>(keys, (const float*)0, 0,
        cc_in_w + (size_t)CD * CD, (size_t)3 * CD * CD,
        cc_in_b + CD, (size_t)3 * CD,
        kv, 0, 0, 2 * CD, CD, 0, 1);
    flash_attn<<<dim3(8, 64, 4), 256, FA_SMEM, s1>>>(q4, CD, 0, TD, kv, 2 * CD, 0, CD,
                                                     km, a4, TD, 0, scale, 1);
    gemm_tc<<<dim3(4, 64, 4), 256, 0, s1>>>(a4, (const float*)0, TD,
                                            cc_out_w, (size_t)CD * CD,
                                            cc_out_b, (size_t)CD,
                                            hid, TD, TOK, CD, CD, 0, 0);
    ln_res4<<<TOK, 256, 0, s1>>>(x, hid, TD, cc_g, cc_b, xcc);
    cudaEventRecord(evB, s1);

    // ---- join + tail (add2 fused into lin1 A-load and final ln) ----
    cudaStreamWaitEvent(0, evB, 0);
    gemm_tc<<<dim3(16, 64), 256>>>(xec, xcc, 0, lin1_w, 0, lin1_b, 0, hid, 0,
                                   TOK, 4 * CD, CD, 1, 0);
    gemm_tc<<<dim3(4, 64), 256>>>(hid, (const float*)0, 0, lin2_w, 0, lin2_b, 0, out2, 0,
                                  TOK, CD, 4 * CD, 0, 0);
    ln_res3<<<TOK, 256>>>(xec, xcc, out2, fu_g, fu_b, out);
}

// round 14
// speedup vs baseline: 1.0890x; 1.0890x over previous
#include <cuda_runtime.h>
#include <math.h>

#define CL   1024
#define CB   8
#define CD   512
#define CH   8
#define CHD  64
#define CLT  32
#define TOK  (CL*CB)          // 8192
#define SUMLK 2081            // 1536+384+107+54
#define KEYTOK (SUMLK*CB)     // 16648

// ---------------- static scratch (allocation-free rule) ----------------
__device__ float g_sent[CB*CD];
__device__ float g_scores[CB*CL];
__device__ int   g_vm[CB*CL];
__device__ int   g_tm[CB*CLT];
__device__ int   g_ecm[CB*CL];
__device__ int   g_km[CB*SUMLK];
__device__ float g_keys[(size_t)KEYTOK*CD];
__device__ float g_qkv[(size_t)TOK*3*CD];      // EC QKV
__device__ float g_kv[(size_t)KEYTOK*2*CD];    // CC KV
__device__ float g_q4[(size_t)4*TOK*CD];
__device__ float g_a4[(size_t)4*TOK*CD];
__device__ float g_attnO[(size_t)TOK*CD];
__device__ float g_t0[(size_t)TOK*CD];
__device__ float g_xec[(size_t)TOK*CD];
__device__ float g_xcc[(size_t)TOK*CD];
__device__ float g_hid[(size_t)TOK*4*CD];
__device__ float g_out2[(size_t)TOK*CD];

__constant__ int cc_Lk[4]  = {1536, 384, 107, 54};
__constant__ int cc_Off[4] = {0, 12288, 15360, 16216};
// pooled-segment tables (8 pools flattened over 2081 positions)
__constant__ int pp_s[8]     = {1, 2, 4, 8, 16, 24, 32, 48};
__constant__ int pp_start[8] = {0, 1024, 1536, 1792, 1920, 1984, 2027, 2059};
__constant__ int pp_coff[8]  = {0, 1024, 0, 256, 0, 64, 0, 32};
__constant__ int pp_grp[8]   = {0, 0, 1, 1, 2, 2, 3, 3};

// ---------------- tf32 helpers ----------------
__device__ __forceinline__ unsigned f2tf32(float x) {
    unsigned r; asm("cvt.rna.tf32.f32 %0, %1;" : "=r"(r) : "f"(x)); return r;
}
__device__ __forceinline__ void mma_tf32(float* d, const unsigned* a, const unsigned* b) {
    asm volatile(
        "mma.sync.aligned.m16n8k8.row.col.f32.tf32.tf32.f32 "
        "{%0,%1,%2,%3}, {%4,%5,%6,%7}, {%8,%9}, {%0,%1,%2,%3};\n"
        : "+f"(d[0]), "+f"(d[1]), "+f"(d[2]), "+f"(d[3])
        : "r"(a[0]), "r"(a[1]), "r"(a[2]), "r"(a[3]),
          "r"(b[0]), "r"(b[1]));
}

// ---------------- mask canonicalization ----------------
__global__ void canon_mask(const void* __restrict__ src, int n, int* __restrict__ dst) {
    unsigned int w = *(const unsigned int*)src;
    int mode = (w == 1u) ? 0 : (w == 0x01010101u) ? 1 : 2;
    for (int i = blockIdx.x * blockDim.x + threadIdx.x; i < n; i += gridDim.x * blockDim.x) {
        int v;
        if (mode == 0)      v = ((const int*)src)[i] != 0;
        else if (mode == 1) v = ((const unsigned char*)src)[i] != 0;
        else                v = ((const float*)src)[i] != 0.f;
        dst[i] = v;
    }
}

// ---------------- sentence-level text pooling ----------------
__global__ void sent_pool(const float* __restrict__ txt, const int* __restrict__ tm,
                          const float* __restrict__ wts_w, const float* __restrict__ wts_b,
                          float* __restrict__ sent) {
    int b = blockIdx.x;
    __shared__ float aw[CLT];
    int tid = threadIdx.x, wid = tid >> 5, lane = tid & 31;
    for (int t = wid; t < CLT; t += 8) {
        const float* row = txt + ((size_t)t * CB + b) * CD;
        float s = 0.f;
        for (int d = lane; d < CD; d += 32) s += row[d] * wts_w[d];
        #pragma unroll
        for (int o = 16; o; o >>= 1) s += __shfl_xor_sync(~0u, s, o);
        if (lane == 0) aw[t] = tm[b * CLT + t] ? s + wts_b[0] : -1e9f;
    }
    __syncthreads();
    if (tid == 0) {
        float mx = -3.4e38f;
        for (int t = 0; t < CLT; t++) mx = fmaxf(mx, aw[t]);
        float sm = 0.f;
        for (int t = 0; t < CLT; t++) { aw[t] = expf(aw[t] - mx); sm += aw[t]; }
        float inv = 1.f / sm;
        for (int t = 0; t < CLT; t++) aw[t] *= inv;
    }
    __syncthreads();
    for (int d = tid; d < CD; d += blockDim.x) {
        float s = 0.f;
        for (int t = 0; t < CLT; t++) s += aw[t] * txt[((size_t)t * CB + b) * CD + d];
        sent[b * CD + d] = s;
    }
}

// ---------------- relevance scores ----------------
__global__ void score_dot(const float* __restrict__ x, const float* __restrict__ sent,
                          const int* __restrict__ vm, float* __restrict__ scores) {
    int w = (blockIdx.x * blockDim.x + threadIdx.x) >> 5;
    int lane = threadIdx.x & 31;
    if (w >= CB * CL) return;
    int b = w & 7, l = w >> 3;
    const float4* xr = (const float4*)(x + ((size_t)(l * CB + b)) * CD);
    const float4* sb = (const float4*)(sent + b * CD);
    float acc = 0.f;
    for (int d = lane; d < CD / 4; d += 32) {
        float4 a = xr[d], c = sb[d];
        acc += a.x * c.x + a.y * c.y + a.z * c.z + a.w * c.w;
    }
    #pragma unroll
    for (int o = 16; o; o >>= 1) acc += __shfl_xor_sync(~0u, acc, o);
    if (lane == 0) {
        if (!vm[b * CL + l]) acc = -1e9f;
        scores[b * CL + l] = acc;
    }
}

// ---------------- exact rank top-k ----------------
__global__ void rank_topk(const float* __restrict__ scores, const int* __restrict__ vm,
                          int* __restrict__ ecm) {
    int b = blockIdx.x, l = threadIdx.x;
    __shared__ float s[CL];
    float mine = scores[b * CL + l];
    s[l] = mine;
    __syncthreads();
    int cnt = 0;
    for (int j = 0; j < CL; j++) {
        float sj = s[j];
        cnt += (sj > mine) || (sj == mine && j < l);
    }
    ecm[b * CL + l] = (cnt >= CL / 2) || !vm[b * CL + l];
}

// ======== tf32 TC GEMM (R8 form, FROZEN): static smem, reg-prefetch, tf32 in smem ========
// mode 0: C[z] = A[z](MxK) @ W[z](NxK)^T + bias[z], strides aZ/wZ/bZ/cZ.
// mode 1 (CC KV): per-z ragged M = cc_Lk[z]*CB, A/C offset by cc_Off[z] rows.
__global__ void gemm_tc(const float* __restrict__ Ab, size_t aZ,
                        const float* __restrict__ Wb, size_t wZ,
                        const float* __restrict__ biasb, size_t bZ,
                        float* __restrict__ Cb, size_t cZ,
                        int M, int N, int K, int relu, int kvmode) {
    __shared__ unsigned As[128][36];   // tf32 bit patterns
    __shared__ unsigned Ws[128][36];
    int z = blockIdx.z;
    const float* A;
    const float* W = Wb + (size_t)z * wZ;
    const float* bias = biasb + (size_t)z * bZ;
    float* C;
    if (kvmode) {
        M = cc_Lk[z] * CB;
        A = Ab + (size_t)cc_Off[z] * CD;
        C = Cb + (size_t)cc_Off[z] * 2 * CD;
    } else {
        A = Ab + (size_t)z * aZ;
        C = Cb + (size_t)z * cZ;
    }

    int row0 = blockIdx.y << 7, col0 = blockIdx.x << 7;
    if (row0 >= M) return;

    int tid = threadIdx.x;
    int wid = tid >> 5, lane = tid & 31;
    int g = lane >> 2, tg = lane & 3;
    int wm = wid >> 2, wn = wid & 3;
    int mb = wm * 64, nb = wn * 32;
    float acc[4][4][4] = {};
    float4 pa[4], pw[4];

    // prefetch chunk 0
    #pragma unroll
    for (int v = 0; v < 4; v++) {
        int idx = tid + v * 256;
        int r = idx >> 3, c4 = idx & 7;
        int gm = row0 + r;
        pa[v] = (gm < M) ? *(const float4*)&A[(size_t)gm * K + c4 * 4]
                         : make_float4(0.f, 0.f, 0.f, 0.f);
        pw[v] = *(const float4*)&W[(size_t)(col0 + r) * K + c4 * 4];
    }

    for (int k0 = 0; k0 < K; k0 += 32) {
        #pragma unroll
        for (int v = 0; v < 4; v++) {
            int idx = tid + v * 256;
            int r = idx >> 3, c4 = idx & 7;
            As[r][c4 * 4 + 0] = f2tf32(pa[v].x); As[r][c4 * 4 + 1] = f2tf32(pa[v].y);
            As[r][c4 * 4 + 2] = f2tf32(pa[v].z); As[r][c4 * 4 + 3] = f2tf32(pa[v].w);
            Ws[r][c4 * 4 + 0] = f2tf32(pw[v].x); Ws[r][c4 * 4 + 1] = f2tf32(pw[v].y);
            Ws[r][c4 * 4 + 2] = f2tf32(pw[v].z); Ws[r][c4 * 4 + 3] = f2tf32(pw[v].w);
        }
        __syncthreads();
        if (k0 + 32 < K) {
            int kn = k0 + 32;
            #pragma unroll
            for (int v = 0; v < 4; v++) {
                int idx = tid + v * 256;
                int r = idx >> 3, c4 = idx & 7;
                int gm = row0 + r;
                pa[v] = (gm < M) ? *(const float4*)&A[(size_t)gm * K + kn + c4 * 4]
                                 : make_float4(0.f, 0.f, 0.f, 0.f);
                pw[v] = *(const float4*)&W[(size_t)(col0 + r) * K + kn + c4 * 4];
            }
        }
        #pragma unroll
        for (int kk = 0; kk < 32; kk += 8) {
            unsigned af[4][4], bf[4][2];
            #pragma unroll
            for (int i = 0; i < 4; i++) {
                int m = mb + i * 16;
                af[i][0] = As[m + g][kk + tg];
                af[i][1] = As[m + g + 8][kk + tg];
                af[i][2] = As[m + g][kk + tg + 4];
                af[i][3] = As[m + g + 8][kk + tg + 4];
            }
            #pragma unroll
            for (int j = 0; j < 4; j++) {
                int n = nb + j * 8;
                bf[j][0] = Ws[n + g][kk + tg];
                bf[j][1] = Ws[n + g][kk + tg + 4];
            }
            #pragma unroll
            for (int i = 0; i < 4; i++)
                #pragma unroll
                for (int j = 0; j < 4; j++) mma_tf32(acc[i][j], af[i], bf[j]);
        }
        __syncthreads();
    }
    #pragma unroll
    for (int i = 0; i < 4; i++) {
        #pragma unroll
        for (int j = 0; j < 4; j++) {
            int gn = col0 + nb + j * 8 + tg * 2;
            float b0 = bias[gn], b1 = bias[gn + 1];
            #pragma unroll
            for (int h = 0; h < 2; h++) {
                int gm = row0 + mb + i * 16 + g + h * 8;
                if (gm >= M) continue;
                float c0 = acc[i][j][h * 2 + 0] + b0;
                float c1 = acc[i][j][h * 2 + 1] + b1;
                if (relu) { c0 = fmaxf(c0, 0.f); c1 = fmaxf(c1, 0.f); }
                *(float2*)&C[(size_t)gm * N + gn] = make_float2(c0, c1);
            }
        }
    }
}

// ======== clone: C = (A1+A2)(MxK) @ W^T + bias, relu — used ONLY for lin1 ========
// M, N, K all multiples of 128/32 at the single call site (8192 x 2048 x 512).
__global__ void gemm_tc_sum(const float* __restrict__ A1, const float* __restrict__ A2,
                            const float* __restrict__ W,
                            const float* __restrict__ bias, float* __restrict__ C,
                            int M, int N, int K, int relu) {
    __shared__ unsigned As[128][36];
    __shared__ unsigned Ws[128][36];
    int row0 = blockIdx.y << 7, col0 = blockIdx.x << 7;

    int tid = threadIdx.x;
    int wid = tid >> 5, lane = tid & 31;
    int g = lane >> 2, tg = lane & 3;
    int wm = wid >> 2, wn = wid & 3;
    int mb = wm * 64, nb = wn * 32;
    float acc[4][4][4] = {};
    float4 pa[4], pw[4];

    #pragma unroll
    for (int v = 0; v < 4; v++) {
        int idx = tid + v * 256;
        int r = idx >> 3, c4 = idx & 7;
        size_t off = (size_t)(row0 + r) * K + c4 * 4;
        float4 a = *(const float4*)&A1[off];
        float4 e = *(const float4*)&A2[off];
        pa[v] = make_float4(a.x + e.x, a.y + e.y, a.z + e.z, a.w + e.w);
        pw[v] = *(const float4*)&W[(size_t)(col0 + r) * K + c4 * 4];
    }

    for (int k0 = 0; k0 < K; k0 += 32) {
        #pragma unroll
        for (int v = 0; v < 4; v++) {
            int idx = tid + v * 256;
            int r = idx >> 3, c4 = idx & 7;
            As[r][c4 * 4 + 0] = f2tf32(pa[v].x); As[r][c4 * 4 + 1] = f2tf32(pa[v].y);
            As[r][c4 * 4 + 2] = f2tf32(pa[v].z); As[r][c4 * 4 + 3] = f2tf32(pa[v].w);
            Ws[r][c4 * 4 + 0] = f2tf32(pw[v].x); Ws[r][c4 * 4 + 1] = f2tf32(pw[v].y);
            Ws[r][c4 * 4 + 2] = f2tf32(pw[v].z); Ws[r][c4 * 4 + 3] = f2tf32(pw[v].w);
        }
        __syncthreads();
        if (k0 + 32 < K) {
            int kn = k0 + 32;
            #pragma unroll
            for (int v = 0; v < 4; v++) {
                int idx = tid + v * 256;
                int r = idx >> 3, c4 = idx & 7;
                size_t off = (size_t)(row0 + r) * K + kn + c4 * 4;
                float4 a = *(const float4*)&A1[off];
                float4 e = *(const float4*)&A2[off];
                pa[v] = make_float4(a.x + e.x, a.y + e.y, a.z + e.z, a.w + e.w);
                pw[v] = *(const float4*)&W[(size_t)(col0 + r) * K + kn + c4 * 4];
            }
        }
        #pragma unroll
        for (int kk = 0; kk < 32; kk += 8) {
            unsigned af[4][4], bf[4][2];
            #pragma unroll
            for (int i = 0; i < 4; i++) {
                int m = mb + i * 16;
                af[i][0] = As[m + g][kk + tg];
                af[i][1] = As[m + g + 8][kk + tg];
                af[i][2] = As[m + g][kk + tg + 4];
                af[i][3] = As[m + g + 8][kk + tg + 4];
            }
            #pragma unroll
            for (int j = 0; j < 4; j++) {
                int n = nb + j * 8;
                bf[j][0] = Ws[n + g][kk + tg];
                bf[j][1] = Ws[n + g][kk + tg + 4];
            }
            #pragma unroll
            for (int i = 0; i < 4; i++)
                #pragma unroll
                for (int j = 0; j < 4; j++) mma_tf32(acc[i][j], af[i], bf[j]);
        }
        __syncthreads();
    }
    #pragma unroll
    for (int i = 0; i < 4; i++) {
        #pragma unroll
        for (int j = 0; j < 4; j++) {
            int gn = col0 + nb + j * 8 + tg * 2;
            float b0 = bias[gn], b1 = bias[gn + 1];
            #pragma unroll
            for (int h = 0; h < 2; h++) {
                int gm = row0 + mb + i * 16 + g + h * 8;
                float c0 = acc[i][j][h * 2 + 0] + b0;
                float c1 = acc[i][j][h * 2 + 1] + b1;
                if (relu) { c0 = fmaxf(c0, 0.f); c1 = fmaxf(c1, 0.f); }
                *(float2*)&C[(size_t)gm * N + gn] = make_float2(c0, c1);
            }
        }
    }
}

// ================= fused flash attention =================
#define FA_QS   0
#define FA_KS   (128*68)
#define FA_VS   (FA_KS + 64*68)
#define FA_PS   (FA_VS + 64*68)
#define FA_KM   (FA_PS + 8*16*68)
#define FA_SMEM ((FA_KM + 64) * 4)

__global__ void __launch_bounds__(256, 2)
flash_attn(const float* __restrict__ Qb, int sQ, int qoff, size_t qZ,
           const float* __restrict__ KVb, int sKV, int koff, int voff,
           const int* __restrict__ ignb, float* __restrict__ Ob, size_t oZ,
           int Lk0, float scale, int multi) {
    extern __shared__ unsigned sm[];
    unsigned* Qs = sm + FA_QS;
    unsigned* Ks = sm + FA_KS;
    unsigned* Vs = sm + FA_VS;
    unsigned* Ps = sm + FA_PS;
    int* kms = (int*)(sm + FA_KM);

    int z = blockIdx.z;
    int Lk = Lk0, rowoff = 0;
    const float* Q = Qb;
    const int* ign = ignb;
    float* O = Ob;
    if (multi) {
        Lk = cc_Lk[z];
        rowoff = cc_Off[z];
        Q = Qb + (size_t)z * qZ;
        O = Ob + (size_t)z * oZ;
        ign = ignb + rowoff;
    }

    int bh = blockIdx.y, b = bh >> 3, h = bh & 7;
    int lq0 = blockIdx.x << 7;
    int tid = threadIdx.x, wid = tid >> 5, lane = tid & 31;
    int g = lane >> 2, tg = lane & 3;
    unsigned* wp = Ps + wid * (16 * 68);
    int mb = wid * 16;

    #pragma unroll
    for (int v = 0; v < 8; v++) {
        int idx = tid + v * 256;
        int r = idx >> 4, c4 = idx & 15;
        float4 q = *(const float4*)&Q[((size_t)((lq0 + r) * CB + b)) * sQ + qoff + h * CHD + c4 * 4];
        Qs[r * 68 + c4 * 4 + 0] = f2tf32(q.x);
        Qs[r * 68 + c4 * 4 + 1] = f2tf32(q.y);
        Qs[r * 68 + c4 * 4 + 2] = f2tf32(q.z);
        Qs[r * 68 + c4 * 4 + 3] = f2tf32(q.w);
    }

    float o[8][4] = {};
    float mA = -1e30f, mB = -1e30f, lA = 0.f, lB = 0.f;

    for (int kt = 0; kt < Lk; kt += 64) {
        __syncthreads();
        #pragma unroll
        for (int v = 0; v < 4; v++) {
            int idx = tid + v * 256;
            int r = idx >> 4, c4 = idx & 15;
            int key = kt + r;
            float4 kv = make_float4(0.f, 0.f, 0.f, 0.f);
            float4 vv = make_float4(0.f, 0.f, 0.f, 0.f);
            if (key < Lk) {
                size_t base = ((size_t)(rowoff + key * CB + b)) * sKV;
                kv = *(const float4*)&KVb[base + koff + h * CHD + c4 * 4];
                vv = *(const float4*)&KVb[base + voff + h * CHD + c4 * 4];
            }
            Ks[r * 68 + c4 * 4 + 0] = f2tf32(kv.x);
            Ks[r * 68 + c4 * 4 + 1] = f2tf32(kv.y);
            Ks[r * 68 + c4 * 4 + 2] = f2tf32(kv.z);
            Ks[r * 68 + c4 * 4 + 3] = f2tf32(kv.w);
            Vs[r * 68 + c4 * 4 + 0] = f2tf32(vv.x);
            Vs[r * 68 + c4 * 4 + 1] = f2tf32(vv.y);
            Vs[r * 68 + c4 * 4 + 2] = f2tf32(vv.z);
            Vs[r * 68 + c4 * 4 + 3] = f2tf32(vv.w);
        }
        if (tid < 64) {
            int key = kt + tid;
            kms[tid] = (key < Lk) ? ign[b * Lk + key] : 1;
        }
        __syncthreads();

        float s[8][4] = {};
        #pragma unroll
        for (int kk = 0; kk < 64; kk += 8) {
            unsigned a[4];
            a[0] = Qs[(mb + g) * 68 + kk + tg];
            a[1] = Qs[(mb + g + 8) * 68 + kk + tg];
            a[2] = Qs[(mb + g) * 68 + kk + tg + 4];
            a[3] = Qs[(mb + g + 8) * 68 + kk + tg + 4];
            #pragma unroll
            for (int j = 0; j < 8; j++) {
                unsigned bfr[2];
                bfr[0] = Ks[(j * 8 + g) * 68 + kk + tg];
                bfr[1] = Ks[(j * 8 + g) * 68 + kk + tg + 4];
                mma_tf32(s[j], a, bfr);
            }
        }
        #pragma unroll
        for (int j = 0; j < 8; j++) {
            int c0 = j * 8 + tg * 2;
            int m0 = kms[c0], m1 = kms[c0 + 1];
            s[j][0] = m0 ? -1e30f : s[j][0] * scale;
            s[j][1] = m1 ? -1e30f : s[j][1] * scale;
            s[j][2] = m0 ? -1e30f : s[j][2] * scale;
            s[j][3] = m1 ? -1e30f : s[j][3] * scale;
        }
        float tA = -3.4e38f, tB = -3.4e38f;
        #pragma unroll
        for (int j = 0; j < 8; j++) {
            tA = fmaxf(tA, fmaxf(s[j][0], s[j][1]));
            tB = fmaxf(tB, fmaxf(s[j][2], s[j][3]));
        }
        #pragma unroll
        for (int off = 1; off <= 2; off <<= 1) {
            tA = fmaxf(tA, __shfl_xor_sync(~0u, tA, off));
            tB = fmaxf(tB, __shfl_xor_sync(~0u, tB, off));
        }
        float mnA = fmaxf(mA, tA), mnB = fmaxf(mB, tB);
        float aA = __expf(mA - mnA), aB = __expf(mB - mnB);
        float suA = 0.f, suB = 0.f;
        #pragma unroll
        for (int j = 0; j < 8; j++) {
            s[j][0] = __expf(s[j][0] - mnA);
            s[j][1] = __expf(s[j][1] - mnA);
            s[j][2] = __expf(s[j][2] - mnB);
            s[j][3] = __expf(s[j][3] - mnB);
            suA += s[j][0] + s[j][1];
            suB += s[j][2] + s[j][3];
        }
        #pragma unroll
        for (int off = 1; off <= 2; off <<= 1) {
            suA += __shfl_xor_sync(~0u, suA, off);
            suB += __shfl_xor_sync(~0u, suB, off);
        }
        lA = lA * aA + suA;  mA = mnA;
        lB = lB * aB + suB;  mB = mnB;
        #pragma unroll
        for (int j = 0; j < 8; j++) {
            o[j][0] *= aA; o[j][1] *= aA;
            o[j][2] *= aB; o[j][3] *= aB;
        }
        #pragma unroll
        for (int j = 0; j < 8; j++) {
            int c0 = j * 8 + tg * 2;
            wp[g * 68 + c0]           = f2tf32(s[j][0]);
            wp[g * 68 + c0 + 1]       = f2tf32(s[j][1]);
            wp[(g + 8) * 68 + c0]     = f2tf32(s[j][2]);
            wp[(g + 8) * 68 + c0 + 1] = f2tf32(s[j][3]);
        }
        __syncwarp();
        #pragma unroll
        for (int kk = 0; kk < 64; kk += 8) {
            unsigned a[4];
            a[0] = wp[g * 68 + kk + tg];
            a[1] = wp[(g + 8) * 68 + kk + tg];
            a[2] = wp[g * 68 + kk + tg + 4];
            a[3] = wp[(g + 8) * 68 + kk + tg + 4];
            #pragma unroll
            for (int j = 0; j < 8; j++) {
                unsigned bfr[2];
                bfr[0] = Vs[(kk + tg) * 68 + j * 8 + g];
                bfr[1] = Vs[(kk + tg + 4) * 68 + j * 8 + g];
                mma_tf32(o[j], a, bfr);
            }
        }
        __syncwarp();
    }
    float iA = 1.f / lA, iB = 1.f / lB;
    int lqA = lq0 + mb + g, lqB = lqA + 8;
    #pragma unroll
    for (int j = 0; j < 8; j++) {
        int c = h * CHD + j * 8 + tg * 2;
        *(float2*)&O[((size_t)(lqA * CB + b)) * CD + c] = make_float2(o[j][0] * iA, o[j][1] * iA);
        *(float2*)&O[((size_t)(lqB * CB + b)) * CD + c] = make_float2(o[j][2] * iB, o[j][3] * iB);
    }
}

// ---------------- all pools in one launch (flattened 2081 positions) ----------------
__global__ void pool_all(const float* __restrict__ x, const int* __restrict__ vm,
                         float* __restrict__ keys, int* __restrict__ kmask) {
    int q = blockIdx.x, b = blockIdx.y;
    int tid = threadIdx.x;
    int p = 7;
    #pragma unroll
    for (int i = 7; i >= 1; i--) if (q < pp_start[i]) p = i - 1;
    int lp = q - pp_start[p];
    int s = pp_s[p];
    int gidx = pp_grp[p];
    int orowIdx = cc_Off[gidx] + (pp_coff[p] + lp) * CB + b;
    size_t orow = (size_t)orowIdx * CD;
    for (int d = tid; d < CD; d += 256) {
        float m = -3.4e38f;
        for (int j = 0; j < s; j++) {
            int l = lp * s + j;
            float v = (l < CL) ? x[((size_t)l * CB + b) * CD + d] : 0.f;
            m = fmaxf(m, v);
        }
        keys[orow + d] = m;
    }
    if (tid == 0) {
        int any = 0;
        for (int j = 0; j < s; j++) {
            int l = lp * s + j;
            if (l < CL && vm[b * CL + l]) any = 1;
        }
        int Lkg = cc_Lk[gidx];
        kmask[cc_Off[gidx] + b * Lkg + (pp_coff[p] + lp)] = !any;
    }
}

// ---------------- LayerNorm(A + R) ----------------
__global__ void ln_res(const float* __restrict__ A, const float* __restrict__ R,
                       const float* __restrict__ g, const float* __restrict__ be,
                       float* __restrict__ out) {
    size_t row = blockIdx.x;
    int tid = threadIdx.x;
    __shared__ float red[256];
    float v0 = A[row * CD + tid]       + R[row * CD + tid];
    float v1 = A[row * CD + tid + 256] + R[row * CD + tid + 256];
    red[tid] = v0 + v1; __syncthreads();
    for (int s = 128; s > 0; s >>= 1) { if (tid < s) red[tid] += red[tid + s]; __syncthreads(); }
    float mu = red[0] / CD; __syncthreads();
    float d0 = v0 - mu, d1 = v1 - mu;
    red[tid] = d0 * d0 + d1 * d1; __syncthreads();
    for (int s = 128; s > 0; s >>= 1) { if (tid < s) red[tid] += red[tid + s]; __syncthreads(); }
    float rstd = rsqrtf(red[0] / CD + 1e-5f);
    out[row * CD + tid]       = d0 * rstd * g[tid]       + be[tid];
    out[row * CD + tid + 256] = d1 * rstd * g[tid + 256] + be[tid + 256];
}

// ---------------- LayerNorm((X1+X2) + R)  — fused add2 + ln ----------------
__global__ void ln_res3(const float* __restrict__ X1, const float* __restrict__ X2,
                        const float* __restrict__ R,
                        const float* __restrict__ g, const float* __restrict__ be,
                        float* __restrict__ out) {
    size_t row = blockIdx.x;
    int tid = threadIdx.x;
    __shared__ float red[256];
    size_t i0 = row * CD + tid, i1 = i0 + 256;
    float v0 = (X1[i0] + X2[i0]) + R[i0];
    float v1 = (X1[i1] + X2[i1]) + R[i1];
    red[tid] = v0 + v1; __syncthreads();
    for (int s = 128; s > 0; s >>= 1) { if (tid < s) red[tid] += red[tid + s]; __syncthreads(); }
    float mu = red[0] / CD; __syncthreads();
    float d0 = v0 - mu, d1 = v1 - mu;
    red[tid] = d0 * d0 + d1 * d1; __syncthreads();
    for (int s = 128; s > 0; s >>= 1) { if (tid < s) red[tid] += red[tid + s]; __syncthreads(); }
    float rstd = rsqrtf(red[0] / CD + 1e-5f);
    out[i0] = d0 * rstd * g[tid]       + be[tid];
    out[i1] = d1 * rstd * g[tid + 256] + be[tid + 256];
}

// ---------------- LayerNorm(x + P0+P1+P2+P3) ----------------
__global__ void ln_res4(const float* __restrict__ X, const float* __restrict__ P, size_t pZ,
                        const float* __restrict__ g, const float* __restrict__ be,
                        float* __restrict__ out) {
    size_t row = blockIdx.x;
    int tid = threadIdx.x;
    __shared__ float red[256];
    size_t i0 = row * CD + tid, i1 = i0 + 256;
    float v0 = X[i0] + P[i0] + P[i0 + pZ] + P[i0 + 2 * pZ] + P[i0 + 3 * pZ];
    float v1 = X[i1] + P[i1] + P[i1 + pZ] + P[i1 + 2 * pZ] + P[i1 + 3 * pZ];
    red[tid] = v0 + v1; __syncthreads();
    for (int s = 128; s > 0; s >>= 1) { if (tid < s) red[tid] += red[tid + s]; __syncthreads(); }
    float mu = red[0] / CD; __syncthreads();
    float d0 = v0 - mu, d1 = v1 - mu;
    red[tid] = d0 * d0 + d1 * d1; __syncthreads();
    for (int s = 128; s > 0; s >>= 1) { if (tid < s) red[tid] += red[tid + s]; __syncthreads(); }
    float rstd = rsqrtf(red[0] / CD + 1e-5f);
    out[i0] = d0 * rstd * g[tid]       + be[tid];
    out[i1] = d1 * rstd * g[tid + 256] + be[tid + 256];
}

// ---------------- launch ----------------
static inline int cdiv(int a, int b) { return (a + b - 1) / b; }

extern "C" void kernel_launch(void* const* d_in, const int* in_sizes, int n_in,
                              void* d_out, int out_size) {
    const float* x        = (const float*)d_in[0];
    const float* txt      = (const float*)d_in[1];
    const void*  vmask    = d_in[2];
    const void*  tmask    = d_in[3];
    const float* wts_w    = (const float*)d_in[4];
    const float* wts_b    = (const float*)d_in[5];
    const float* ec_in_w  = (const float*)d_in[6];
    const float* ec_in_b  = (const float*)d_in[7];
    const float* ec_out_w = (const float*)d_in[8];
    const float* ec_out_b = (const float*)d_in[9];
    const float* cc_in_w  = (const float*)d_in[10];
    const float* cc_in_b  = (const float*)d_in[11];
    const float* cc_out_w = (const float*)d_in[12];
    const float* cc_out_b = (const float*)d_in[13];
    const float* ec_g     = (const float*)d_in[14];
    const float* ec_b     = (const float*)d_in[15];
    const float* cc_g     = (const float*)d_in[16];
    const float* cc_b     = (const float*)d_in[17];
    const float* fu_g     = (const float*)d_in[18];
    const float* fu_b     = (const float*)d_in[19];
    const float* lin1_w   = (const float*)d_in[20];
    const float* lin1_b   = (const float*)d_in[21];
    const float* lin2_w   = (const float*)d_in[22];
    const float* lin2_b   = (const float*)d_in[23];
    float* out = (float*)d_out;

    static int init_done = 0;
    static cudaStream_t s1, s2;
    static cudaEvent_t evFork, evVm, evB, evTopk;
    if (!init_done) {
        cudaFuncSetAttribute(flash_attn, cudaFuncAttributeMaxDynamicSharedMemorySize, FA_SMEM);
        cudaStreamCreateWithFlags(&s1, cudaStreamNonBlocking);
        cudaStreamCreateWithFlags(&s2, cudaStreamNonBlocking);
        cudaEventCreateWithFlags(&evFork, cudaEventDisableTiming);
        cudaEventCreateWithFlags(&evVm,   cudaEventDisableTiming);
        cudaEventCreateWithFlags(&evB,    cudaEventDisableTiming);
        cudaEventCreateWithFlags(&evTopk, cudaEventDisableTiming);
        init_done = 1;
    }

    float *sent, *scores, *keys, *qkv, *kv, *q4, *a4, *aO, *t0, *xec, *xcc, *hid, *out2;
    int *vm, *tm, *ecm, *km;
    cudaGetSymbolAddress((void**)&sent,   g_sent);
    cudaGetSymbolAddress((void**)&scores, g_scores);
    cudaGetSymbolAddress((void**)&vm,     g_vm);
    cudaGetSymbolAddress((void**)&tm,     g_tm);
    cudaGetSymbolAddress((void**)&ecm,    g_ecm);
    cudaGetSymbolAddress((void**)&km,     g_km);
    cudaGetSymbolAddress((void**)&keys,   g_keys);
    cudaGetSymbolAddress((void**)&qkv,    g_qkv);
    cudaGetSymbolAddress((void**)&kv,     g_kv);
    cudaGetSymbolAddress((void**)&q4,     g_q4);
    cudaGetSymbolAddress((void**)&a4,     g_a4);
    cudaGetSymbolAddress((void**)&aO,     g_attnO);
    cudaGetSymbolAddress((void**)&t0,     g_t0);
    cudaGetSymbolAddress((void**)&xec,    g_xec);
    cudaGetSymbolAddress((void**)&xcc,    g_xcc);
    cudaGetSymbolAddress((void**)&hid,    g_hid);
    cudaGetSymbolAddress((void**)&out2,   g_out2);

    const float scale = 0.125f;   // 1/sqrt(64)
    const size_t TD = (size_t)TOK * CD;

    // ---- fork ----
    cudaEventRecord(evFork, 0);
    cudaStreamWaitEvent(s1, evFork, 0);
    cudaStreamWaitEvent(s2, evFork, 0);

    // ---- stream 0: vm + EC gemms/flash ----
    canon_mask<<<32, 256>>>(vmask, CB * CL, vm);
    cudaEventRecord(evVm, 0);
    gemm_tc<<<dim3(12, 64), 256>>>(x, 0, ec_in_w, 0, ec_in_b, 0, qkv, 0,
                                   TOK, 3 * CD, CD, 0, 0);

    // ---- stream s2: topk chain (overlaps with QKV gemm) ----
    canon_mask<<<1, 256, 0, s2>>>(tmask, CB * CLT, tm);
    sent_pool<<<CB, 256, 0, s2>>>(txt, tm, wts_w, wts_b, sent);
    cudaStreamWaitEvent(s2, evVm, 0);
    score_dot<<<1024, 256, 0, s2>>>(x, sent, vm, scores);
    rank_topk<<<CB, 1024, 0, s2>>>(scores, vm, ecm);
    cudaEventRecord(evTopk, s2);

    cudaStreamWaitEvent(0, evTopk, 0);
    flash_attn<<<dim3(8, 64, 1), 256, FA_SMEM>>>(qkv, 3 * CD, 0, 0, qkv, 3 * CD, CD, 2 * CD,
                                                 ecm, aO, 0, CL, scale, 0);
    gemm_tc<<<dim3(4, 64), 256>>>(aO, 0, ec_out_w, 0, ec_out_b, 0, t0, 0,
                                  TOK, CD, CD, 0, 0);
    ln_res<<<TOK, 256>>>(x, t0, ec_g, ec_b, xec);

    // ---- stream s1: CC branch ----
    gemm_tc<<<dim3(4, 64, 4), 256, 0, s1>>>(x, 0,
                                            cc_in_w, (size_t)3 * CD * CD,
                                            cc_in_b, (size_t)3 * CD,
                                            q4, TD, TOK, CD, CD, 0, 0);
    cudaStreamWaitEvent(s1, evVm, 0);
    pool_all<<<dim3(SUMLK, CB), 256, 0, s1>>>(x, vm, keys, km);
    gemm_tc<<<dim3(8, 96, 4), 256, 0, s1>>>(keys, 0,
        cc_in_w + (size_t)CD * CD, (size_t)3 * CD * CD,
        cc_in_b + CD, (size_t)3 * CD,
        kv, 0, 0, 2 * CD, CD, 0, 1);
    flash_attn<<<dim3(8, 64, 4), 256, FA_SMEM, s1>>>(q4, CD, 0, TD, kv, 2 * CD, 0, CD,
                                                     km, a4, TD, 0, scale, 1);
    gemm_tc<<<dim3(4, 64, 4), 256, 0, s1>>>(a4, TD,
                                            cc_out_w, (size_t)CD * CD,
                                            cc_out_b, (size_t)CD,
                                            hid, TD, TOK, CD, CD, 0, 0);
    ln_res4<<<TOK, 256, 0, s1>>>(x, hid, TD, cc_g, cc_b, xcc);
    cudaEventRecord(evB, s1);

    // ---- join + tail (add2 fused into lin1 clone + final ln) ----
    cudaStreamWaitEvent(0, evB, 0);
    gemm_tc_sum<<<dim3(16, 64), 256>>>(xec, xcc, lin1_w, lin1_b, hid,
                                       TOK, 4 * CD, CD, 1);
    gemm_tc<<<dim3(4, 64), 256>>>(hid, 0, lin2_w, 0, lin2_b, 0, out2, 0,
                                  TOK, CD, 4 * CD, 0, 0);
    ln_res3<<<TOK, 256>>>(xec, xcc, out2, fu_g, fu_b, out);
}

// round 16
// speedup vs baseline: 1.1255x; 1.0335x over previous
#include <cuda_runtime.h>
#include <math.h>

#define CL   1024
#define CB   8
#define CD   512
#define CH   8
#define CHD  64
#define CLT  32
#define TOK  (CL*CB)          // 8192
#define SUMLK 2081            // 1536+384+107+54
#define KEYTOK (SUMLK*CB)     // 16648

// ---------------- static scratch (allocation-free rule) ----------------
__device__ float g_sent[CB*CD];
__device__ float g_scores[CB*CL];
__device__ int   g_vm[CB*CL];
__device__ int   g_tm[CB*CLT];
__device__ int   g_ecm[CB*CL];
__device__ int   g_km[CB*SUMLK];
__device__ float g_keys[(size_t)KEYTOK*CD];
__device__ float g_qkv[(size_t)TOK*3*CD];      // EC QKV
__device__ float g_kv[(size_t)KEYTOK*2*CD];    // CC KV
__device__ float g_q4[(size_t)4*TOK*CD];
__device__ float g_a4[(size_t)4*TOK*CD];
__device__ float g_attnO[(size_t)TOK*CD];
__device__ float g_t0[(size_t)TOK*CD];
__device__ float g_xec[(size_t)TOK*CD];
__device__ float g_xcc[(size_t)TOK*CD];
__device__ float g_out[(size_t)TOK*CD];
__device__ float g_hid[(size_t)TOK*4*CD];
__device__ float g_out2[(size_t)TOK*CD];

__constant__ int cc_Lk[4]  = {1536, 384, 107, 54};
__constant__ int cc_Off[4] = {0, 12288, 15360, 16216};
// pooled-segment tables (8 pools flattened over 2081 positions)
__constant__ int pp_s[8]     = {1, 2, 4, 8, 16, 24, 32, 48};
__constant__ int pp_start[8] = {0, 1024, 1536, 1792, 1920, 1984, 2027, 2059};
__constant__ int pp_coff[8]  = {0, 1024, 0, 256, 0, 64, 0, 32};
__constant__ int pp_grp[8]   = {0, 0, 1, 1, 2, 2, 3, 3};

// ---------------- tf32 helpers ----------------
__device__ __forceinline__ unsigned f2tf32(float x) {
    unsigned r; asm("cvt.rna.tf32.f32 %0, %1;" : "=r"(r) : "f"(x)); return r;
}
__device__ __forceinline__ void mma_tf32(float* d, const unsigned* a, const unsigned* b) {
    asm volatile(
        "mma.sync.aligned.m16n8k8.row.col.f32.tf32.tf32.f32 "
        "{%0,%1,%2,%3}, {%4,%5,%6,%7}, {%8,%9}, {%0,%1,%2,%3};\n"
        : "+f"(d[0]), "+f"(d[1]), "+f"(d[2]), "+f"(d[3])
        : "r"(a[0]), "r"(a[1]), "r"(a[2]), "r"(a[3]),
          "r"(b[0]), "r"(b[1]));
}

// ---------------- mask canonicalization ----------------
__global__ void canon_mask(const void* __restrict__ src, int n, int* __restrict__ dst) {
    unsigned int w = *(const unsigned int*)src;
    int mode = (w == 1u) ? 0 : (w == 0x01010101u) ? 1 : 2;
    for (int i = blockIdx.x * blockDim.x + threadIdx.x; i < n; i += gridDim.x * blockDim.x) {
        int v;
        if (mode == 0)      v = ((const int*)src)[i] != 0;
        else if (mode == 1) v = ((const unsigned char*)src)[i] != 0;
        else                v = ((const float*)src)[i] != 0.f;
        dst[i] = v;
    }
}

// ---------------- sentence-level text pooling ----------------
__global__ void sent_pool(const float* __restrict__ txt, const int* __restrict__ tm,
                          const float* __restrict__ wts_w, const float* __restrict__ wts_b,
                          float* __restrict__ sent) {
    int b = blockIdx.x;
    __shared__ float aw[CLT];
    int tid = threadIdx.x, wid = tid >> 5, lane = tid & 31;
    for (int t = wid; t < CLT; t += 8) {
        const float* row = txt + ((size_t)t * CB + b) * CD;
        float s = 0.f;
        for (int d = lane; d < CD; d += 32) s += row[d] * wts_w[d];
        #pragma unroll
        for (int o = 16; o; o >>= 1) s += __shfl_xor_sync(~0u, s, o);
        if (lane == 0) aw[t] = tm[b * CLT + t] ? s + wts_b[0] : -1e9f;
    }
    __syncthreads();
    if (tid == 0) {
        float mx = -3.4e38f;
        for (int t = 0; t < CLT; t++) mx = fmaxf(mx, aw[t]);
        float sm = 0.f;
        for (int t = 0; t < CLT; t++) { aw[t] = expf(aw[t] - mx); sm += aw[t]; }
        float inv = 1.f / sm;
        for (int t = 0; t < CLT; t++) aw[t] *= inv;
    }
    __syncthreads();
    for (int d = tid; d < CD; d += blockDim.x) {
        float s = 0.f;
        for (int t = 0; t < CLT; t++) s += aw[t] * txt[((size_t)t * CB + b) * CD + d];
        sent[b * CD + d] = s;
    }
}

// ---------------- relevance scores ----------------
__global__ void score_dot(const float* __restrict__ x, const float* __restrict__ sent,
                          const int* __restrict__ vm, float* __restrict__ scores) {
    int w = (blockIdx.x * blockDim.x + threadIdx.x) >> 5;
    int lane = threadIdx.x & 31;
    if (w >= CB * CL) return;
    int b = w & 7, l = w >> 3;
    const float4* xr = (const float4*)(x + ((size_t)(l * CB + b)) * CD);
    const float4* sb = (const float4*)(sent + b * CD);
    float acc = 0.f;
    for (int d = lane; d < CD / 4; d += 32) {
        float4 a = xr[d], c = sb[d];
        acc += a.x * c.x + a.y * c.y + a.z * c.z + a.w * c.w;
    }
    #pragma unroll
    for (int o = 16; o; o >>= 1) acc += __shfl_xor_sync(~0u, acc, o);
    if (lane == 0) {
        if (!vm[b * CL + l]) acc = -1e9f;
        scores[b * CL + l] = acc;
    }
}

// ---------------- exact rank top-k ----------------
__global__ void rank_topk(const float* __restrict__ scores, const int* __restrict__ vm,
                          int* __restrict__ ecm) {
    int b = blockIdx.x, l = threadIdx.x;
    __shared__ float s[CL];
    float mine = scores[b * CL + l];
    s[l] = mine;
    __syncthreads();
    int cnt = 0;
    for (int j = 0; j < CL; j++) {
        float sj = s[j];
        cnt += (sj > mine) || (sj == mine && j < l);
    }
    ecm[b * CL + l] = (cnt >= CL / 2) || !vm[b * CL + l];
}

// ======== tf32 TC GEMM (R8 form, FROZEN): static smem, reg-prefetch, tf32 in smem ========
// mode 0: C[z] = A[z](MxK) @ W[z](NxK)^T + bias[z], strides aZ/wZ/bZ/cZ.
// mode 1 (CC KV): per-z ragged M = cc_Lk[z]*CB, A/C offset by cc_Off[z] rows.
__global__ void gemm_tc(const float* __restrict__ Ab, size_t aZ,
                        const float* __restrict__ Wb, size_t wZ,
                        const float* __restrict__ biasb, size_t bZ,
                        float* __restrict__ Cb, size_t cZ,
                        int M, int N, int K, int relu, int kvmode) {
    __shared__ unsigned As[128][36];   // tf32 bit patterns
    __shared__ unsigned Ws[128][36];
    int z = blockIdx.z;
    const float* A;
    const float* W = Wb + (size_t)z * wZ;
    const float* bias = biasb + (size_t)z * bZ;
    float* C;
    if (kvmode) {
        M = cc_Lk[z] * CB;
        A = Ab + (size_t)cc_Off[z] * CD;
        C = Cb + (size_t)cc_Off[z] * 2 * CD;
    } else {
        A = Ab + (size_t)z * aZ;
        C = Cb + (size_t)z * cZ;
    }

    int row0 = blockIdx.y << 7, col0 = blockIdx.x << 7;
    if (row0 >= M) return;

    int tid = threadIdx.x;
    int wid = tid >> 5, lane = tid & 31;
    int g = lane >> 2, tg = lane & 3;
    int wm = wid >> 2, wn = wid & 3;
    int mb = wm * 64, nb = wn * 32;
    float acc[4][4][4] = {};
    float4 pa[4], pw[4];

    // prefetch chunk 0
    #pragma unroll
    for (int v = 0; v < 4; v++) {
        int idx = tid + v * 256;
        int r = idx >> 3, c4 = idx & 7;
        int gm = row0 + r;
        pa[v] = (gm < M) ? *(const float4*)&A[(size_t)gm * K + c4 * 4]
                         : make_float4(0.f, 0.f, 0.f, 0.f);
        pw[v] = *(const float4*)&W[(size_t)(col0 + r) * K + c4 * 4];
    }

    for (int k0 = 0; k0 < K; k0 += 32) {
        #pragma unroll
        for (int v = 0; v < 4; v++) {
            int idx = tid + v * 256;
            int r = idx >> 3, c4 = idx & 7;
            As[r][c4 * 4 + 0] = f2tf32(pa[v].x); As[r][c4 * 4 + 1] = f2tf32(pa[v].y);
            As[r][c4 * 4 + 2] = f2tf32(pa[v].z); As[r][c4 * 4 + 3] = f2tf32(pa[v].w);
            Ws[r][c4 * 4 + 0] = f2tf32(pw[v].x); Ws[r][c4 * 4 + 1] = f2tf32(pw[v].y);
            Ws[r][c4 * 4 + 2] = f2tf32(pw[v].z); Ws[r][c4 * 4 + 3] = f2tf32(pw[v].w);
        }
        __syncthreads();
        if (k0 + 32 < K) {
            int kn = k0 + 32;
            #pragma unroll
            for (int v = 0; v < 4; v++) {
                int idx = tid + v * 256;
                int r = idx >> 3, c4 = idx & 7;
                int gm = row0 + r;
                pa[v] = (gm < M) ? *(const float4*)&A[(size_t)gm * K + kn + c4 * 4]
                                 : make_float4(0.f, 0.f, 0.f, 0.f);
                pw[v] = *(const float4*)&W[(size_t)(col0 + r) * K + kn + c4 * 4];
            }
        }
        #pragma unroll
        for (int kk = 0; kk < 32; kk += 8) {
            unsigned af[4][4], bf[4][2];
            #pragma unroll
            for (int i = 0; i < 4; i++) {
                int m = mb + i * 16;
                af[i][0] = As[m + g][kk + tg];
                af[i][1] = As[m + g + 8][kk + tg];
                af[i][2] = As[m + g][kk + tg + 4];
                af[i][3] = As[m + g + 8][kk + tg + 4];
            }
            #pragma unroll
            for (int j = 0; j < 4; j++) {
                int n = nb + j * 8;
                bf[j][0] = Ws[n + g][kk + tg];
                bf[j][1] = Ws[n + g][kk + tg + 4];
            }
            #pragma unroll
            for (int i = 0; i < 4; i++)
                #pragma unroll
                for (int j = 0; j < 4; j++) mma_tf32(acc[i][j], af[i], bf[j]);
        }
        __syncthreads();
    }
    #pragma unroll
    for (int i = 0; i < 4; i++) {
        #pragma unroll
        for (int j = 0; j < 4; j++) {
            int gn = col0 + nb + j * 8 + tg * 2;
            float b0 = bias[gn], b1 = bias[gn + 1];
            #pragma unroll
            for (int h = 0; h < 2; h++) {
                int gm = row0 + mb + i * 16 + g + h * 8;
                if (gm >= M) continue;
                float c0 = acc[i][j][h * 2 + 0] + b0;
                float c1 = acc[i][j][h * 2 + 1] + b1;
                if (relu) { c0 = fmaxf(c0, 0.f); c1 = fmaxf(c1, 0.f); }
                *(float2*)&C[(size_t)gm * N + gn] = make_float2(c0, c1);
            }
        }
    }
}

// ================= fused flash attention =================
#define FA_QS   0
#define FA_KS   (128*68)
#define FA_VS   (FA_KS + 64*68)
#define FA_PS   (FA_VS + 64*68)
#define FA_KM   (FA_PS + 8*16*68)
#define FA_SMEM ((FA_KM + 64) * 4)

__global__ void __launch_bounds__(256, 2)
flash_attn(const float* __restrict__ Qb, int sQ, int qoff, size_t qZ,
           const float* __restrict__ KVb, int sKV, int koff, int voff,
           const int* __restrict__ ignb, float* __restrict__ Ob, size_t oZ,
           int Lk0, float scale, int multi) {
    extern __shared__ unsigned sm[];
    unsigned* Qs = sm + FA_QS;
    unsigned* Ks = sm + FA_KS;
    unsigned* Vs = sm + FA_VS;
    unsigned* Ps = sm + FA_PS;
    int* kms = (int*)(sm + FA_KM);

    int z = blockIdx.z;
    int Lk = Lk0, rowoff = 0;
    const float* Q = Qb;
    const int* ign = ignb;
    float* O = Ob;
    if (multi) {
        Lk = cc_Lk[z];
        rowoff = cc_Off[z];
        Q = Qb + (size_t)z * qZ;
        O = Ob + (size_t)z * oZ;
        ign = ignb + rowoff;
    }

    int bh = blockIdx.y, b = bh >> 3, h = bh & 7;
    int lq0 = blockIdx.x << 7;
    int tid = threadIdx.x, wid = tid >> 5, lane = tid & 31;
    int g = lane >> 2, tg = lane & 3;
    unsigned* wp = Ps + wid * (16 * 68);
    int mb = wid * 16;

    #pragma unroll
    for (int v = 0; v < 8; v++) {
        int idx = tid + v * 256;
        int r = idx >> 4, c4 = idx & 15;
        float4 q = *(const float4*)&Q[((size_t)((lq0 + r) * CB + b)) * sQ + qoff + h * CHD + c4 * 4];
        Qs[r * 68 + c4 * 4 + 0] = f2tf32(q.x);
        Qs[r * 68 + c4 * 4 + 1] = f2tf32(q.y);
        Qs[r * 68 + c4 * 4 + 2] = f2tf32(q.z);
        Qs[r * 68 + c4 * 4 + 3] = f2tf32(q.w);
    }

    float o[8][4] = {};
    float mA = -1e30f, mB = -1e30f, lA = 0.f, lB = 0.f;

    for (int kt = 0; kt < Lk; kt += 64) {
        __syncthreads();
        #pragma unroll
        for (int v = 0; v < 4; v++) {
            int idx = tid + v * 256;
            int r = idx >> 4, c4 = idx & 15;
            int key = kt + r;
            float4 kv = make_float4(0.f, 0.f, 0.f, 0.f);
            float4 vv = make_float4(0.f, 0.f, 0.f, 0.f);
            if (key < Lk) {
                size_t base = ((size_t)(rowoff + key * CB + b)) * sKV;
                kv = *(const float4*)&KVb[base + koff + h * CHD + c4 * 4];
                vv = *(const float4*)&KVb[base + voff + h * CHD + c4 * 4];
            }
            Ks[r * 68 + c4 * 4 + 0] = f2tf32(kv.x);
            Ks[r * 68 + c4 * 4 + 1] = f2tf32(kv.y);
            Ks[r * 68 + c4 * 4 + 2] = f2tf32(kv.z);
            Ks[r * 68 + c4 * 4 + 3] = f2tf32(kv.w);
            Vs[r * 68 + c4 * 4 + 0] = f2tf32(vv.x);
            Vs[r * 68 + c4 * 4 + 1] = f2tf32(vv.y);
            Vs[r * 68 + c4 * 4 + 2] = f2tf32(vv.z);
            Vs[r * 68 + c4 * 4 + 3] = f2tf32(vv.w);
        }
        if (tid < 64) {
            int key = kt + tid;
            kms[tid] = (key < Lk) ? ign[b * Lk + key] : 1;
        }
        __syncthreads();

        float s[8][4] = {};
        #pragma unroll
        for (int kk = 0; kk < 64; kk += 8) {
            unsigned a[4];
            a[0] = Qs[(mb + g) * 68 + kk + tg];
            a[1] = Qs[(mb + g + 8) * 68 + kk + tg];
            a[2] = Qs[(mb + g) * 68 + kk + tg + 4];
            a[3] = Qs[(mb + g + 8) * 68 + kk + tg + 4];
            #pragma unroll
            for (int j = 0; j < 8; j++) {
                unsigned bfr[2];
                bfr[0] = Ks[(j * 8 + g) * 68 + kk + tg];
                bfr[1] = Ks[(j * 8 + g) * 68 + kk + tg + 4];
                mma_tf32(s[j], a, bfr);
            }
        }
        #pragma unroll
        for (int j = 0; j < 8; j++) {
            int c0 = j * 8 + tg * 2;
            int m0 = kms[c0], m1 = kms[c0 + 1];
            s[j][0] = m0 ? -1e30f : s[j][0] * scale;
            s[j][1] = m1 ? -1e30f : s[j][1] * scale;
            s[j][2] = m0 ? -1e30f : s[j][2] * scale;
            s[j][3] = m1 ? -1e30f : s[j][3] * scale;
        }
        float tA = -3.4e38f, tB = -3.4e38f;
        #pragma unroll
        for (int j = 0; j < 8; j++) {
            tA = fmaxf(tA, fmaxf(s[j][0], s[j][1]));
            tB = fmaxf(tB, fmaxf(s[j][2], s[j][3]));
        }
        #pragma unroll
        for (int off = 1; off <= 2; off <<= 1) {
            tA = fmaxf(tA, __shfl_xor_sync(~0u, tA, off));
            tB = fmaxf(tB, __shfl_xor_sync(~0u, tB, off));
        }
        float mnA = fmaxf(mA, tA), mnB = fmaxf(mB, tB);
        float aA = __expf(mA - mnA), aB = __expf(mB - mnB);
        float suA = 0.f, suB = 0.f;
        #pragma unroll
        for (int j = 0; j < 8; j++) {
            s[j][0] = __expf(s[j][0] - mnA);
            s[j][1] = __expf(s[j][1] - mnA);
            s[j][2] = __expf(s[j][2] - mnB);
            s[j][3] = __expf(s[j][3] - mnB);
            suA += s[j][0] + s[j][1];
            suB += s[j][2] + s[j][3];
        }
        #pragma unroll
        for (int off = 1; off <= 2; off <<= 1) {
            suA += __shfl_xor_sync(~0u, suA, off);
            suB += __shfl_xor_sync(~0u, suB, off);
        }
        lA = lA * aA + suA;  mA = mnA;
        lB = lB * aB + suB;  mB = mnB;
        #pragma unroll
        for (int j = 0; j < 8; j++) {
            o[j][0] *= aA; o[j][1] *= aA;
            o[j][2] *= aB; o[j][3] *= aB;
        }
        #pragma unroll
        for (int j = 0; j < 8; j++) {
            int c0 = j * 8 + tg * 2;
            wp[g * 68 + c0]           = f2tf32(s[j][0]);
            wp[g * 68 + c0 + 1]       = f2tf32(s[j][1]);
            wp[(g + 8) * 68 + c0]     = f2tf32(s[j][2]);
            wp[(g + 8) * 68 + c0 + 1] = f2tf32(s[j][3]);
        }
        __syncwarp();
        #pragma unroll
        for (int kk = 0; kk < 64; kk += 8) {
            unsigned a[4];
            a[0] = wp[g * 68 + kk + tg];
            a[1] = wp[(g + 8) * 68 + kk + tg];
            a[2] = wp[g * 68 + kk + tg + 4];
            a[3] = wp[(g + 8) * 68 + kk + tg + 4];
            #pragma unroll
            for (int j = 0; j < 8; j++) {
                unsigned bfr[2];
                bfr[0] = Vs[(kk + tg) * 68 + j * 8 + g];
                bfr[1] = Vs[(kk + tg + 4) * 68 + j * 8 + g];
                mma_tf32(o[j], a, bfr);
            }
        }
        __syncwarp();
    }
    float iA = 1.f / lA, iB = 1.f / lB;
    int lqA = lq0 + mb + g, lqB = lqA + 8;
    #pragma unroll
    for (int j = 0; j < 8; j++) {
        int c = h * CHD + j * 8 + tg * 2;
        *(float2*)&O[((size_t)(lqA * CB + b)) * CD + c] = make_float2(o[j][0] * iA, o[j][1] * iA);
        *(float2*)&O[((size_t)(lqB * CB + b)) * CD + c] = make_float2(o[j][2] * iB, o[j][3] * iB);
    }
}

// ---------------- all pools in one launch (flattened 2081 positions) ----------------
__global__ void pool_all(const float* __restrict__ x, const int* __restrict__ vm,
                         float* __restrict__ keys, int* __restrict__ kmask) {
    int q = blockIdx.x, b = blockIdx.y;
    int tid = threadIdx.x;
    int p = 7;
    #pragma unroll
    for (int i = 7; i >= 1; i--) if (q < pp_start[i]) p = i - 1;
    int lp = q - pp_start[p];
    int s = pp_s[p];
    int gidx = pp_grp[p];
    int orowIdx = cc_Off[gidx] + (pp_coff[p] + lp) * CB + b;
    size_t orow = (size_t)orowIdx * CD;
    for (int d = tid; d < CD; d += 256) {
        float m = -3.4e38f;
        for (int j = 0; j < s; j++) {
            int l = lp * s + j;
            float v = (l < CL) ? x[((size_t)l * CB + b) * CD + d] : 0.f;
            m = fmaxf(m, v);
        }
        keys[orow + d] = m;
    }
    if (tid == 0) {
        int any = 0;
        for (int j = 0; j < s; j++) {
            int l = lp * s + j;
            if (l < CL && vm[b * CL + l]) any = 1;
        }
        int Lkg = cc_Lk[gidx];
        kmask[cc_Off[gidx] + b * Lkg + (pp_coff[p] + lp)] = !any;
    }
}

// ---------------- LayerNorm(A + R) ----------------
__global__ void ln_res(const float* __restrict__ A, const float* __restrict__ R,
                       const float* __restrict__ g, const float* __restrict__ be,
                       float* __restrict__ out) {
    size_t row = blockIdx.x;
    int tid = threadIdx.x;
    __shared__ float red[256];
    float v0 = A[row * CD + tid]       + R[row * CD + tid];
    float v1 = A[row * CD + tid + 256] + R[row * CD + tid + 256];
    red[tid] = v0 + v1; __syncthreads();
    for (int s = 128; s > 0; s >>= 1) { if (tid < s) red[tid] += red[tid + s]; __syncthreads(); }
    float mu = red[0] / CD; __syncthreads();
    float d0 = v0 - mu, d1 = v1 - mu;
    red[tid] = d0 * d0 + d1 * d1; __syncthreads();
    for (int s = 128; s > 0; s >>= 1) { if (tid < s) red[tid] += red[tid + s]; __syncthreads(); }
    float rstd = rsqrtf(red[0] / CD + 1e-5f);
    out[row * CD + tid]       = d0 * rstd * g[tid]       + be[tid];
    out[row * CD + tid + 256] = d1 * rstd * g[tid + 256] + be[tid + 256];
}

// ---------------- LayerNorm(x + P0+P1+P2+P3) ----------------
__global__ void ln_res4(const float* __restrict__ X, const float* __restrict__ P, size_t pZ,
                        const float* __restrict__ g, const float* __restrict__ be,
                        float* __restrict__ out) {
    size_t row = blockIdx.x;
    int tid = threadIdx.x;
    __shared__ float red[256];
    size_t i0 = row * CD + tid, i1 = i0 + 256;
    float v0 = X[i0] + P[i0] + P[i0 + pZ] + P[i0 + 2 * pZ] + P[i0 + 3 * pZ];
    float v1 = X[i1] + P[i1] + P[i1 + pZ] + P[i1 + 2 * pZ] + P[i1 + 3 * pZ];
    red[tid] = v0 + v1; __syncthreads();
    for (int s = 128; s > 0; s >>= 1) { if (tid < s) red[tid] += red[tid + s]; __syncthreads(); }
    float mu = red[0] / CD; __syncthreads();
    float d0 = v0 - mu, d1 = v1 - mu;
    red[tid] = d0 * d0 + d1 * d1; __syncthreads();
    for (int s = 128; s > 0; s >>= 1) { if (tid < s) red[tid] += red[tid + s]; __syncthreads(); }
    float rstd = rsqrtf(red[0] / CD + 1e-5f);
    out[i0] = d0 * rstd * g[tid]       + be[tid];
    out[i1] = d1 * rstd * g[tid + 256] + be[tid + 256];
}

__global__ void add2(const float* __restrict__ a, const float* __restrict__ b,
                     float* __restrict__ c, int n) {
    for (int i = blockIdx.x * blockDim.x + threadIdx.x; i < n; i += gridDim.x * blockDim.x)
        c[i] = a[i] + b[i];
}

// ---------------- launch ----------------
static inline int cdiv(int a, int b) { return (a + b - 1) / b; }

extern "C" void kernel_launch(void* const* d_in, const int* in_sizes, int n_in,
                              void* d_out, int out_size) {
    const float* x        = (const float*)d_in[0];
    const float* txt      = (const float*)d_in[1];
    const void*  vmask    = d_in[2];
    const void*  tmask    = d_in[3];
    const float* wts_w    = (const float*)d_in[4];
    const float* wts_b    = (const float*)d_in[5];
    const float* ec_in_w  = (const float*)d_in[6];
    const float* ec_in_b  = (const float*)d_in[7];
    const float* ec_out_w = (const float*)d_in[8];
    const float* ec_out_b = (const float*)d_in[9];
    const float* cc_in_w  = (const float*)d_in[10];
    const float* cc_in_b  = (const float*)d_in[11];
    const float* cc_out_w = (const float*)d_in[12];
    const float* cc_out_b = (const float*)d_in[13];
    const float* ec_g     = (const float*)d_in[14];
    const float* ec_b     = (const float*)d_in[15];
    const float* cc_g     = (const float*)d_in[16];
    const float* cc_b     = (const float*)d_in[17];
    const float* fu_g     = (const float*)d_in[18];
    const float* fu_b     = (const float*)d_in[19];
    const float* lin1_w   = (const float*)d_in[20];
    const float* lin1_b   = (const float*)d_in[21];
    const float* lin2_w   = (const float*)d_in[22];
    const float* lin2_b   = (const float*)d_in[23];
    float* out = (float*)d_out;

    static int init_done = 0;
    static cudaStream_t s1, s2;
    static cudaEvent_t evFork, evVm, evB, evTopk;
    if (!init_done) {
        cudaFuncSetAttribute(flash_attn, cudaFuncAttributeMaxDynamicSharedMemorySize, FA_SMEM);
        cudaStreamCreateWithFlags(&s1, cudaStreamNonBlocking);
        cudaStreamCreateWithFlags(&s2, cudaStreamNonBlocking);
        cudaEventCreateWithFlags(&evFork, cudaEventDisableTiming);
        cudaEventCreateWithFlags(&evVm,   cudaEventDisableTiming);
        cudaEventCreateWithFlags(&evB,    cudaEventDisableTiming);
        cudaEventCreateWithFlags(&evTopk, cudaEventDisableTiming);
        init_done = 1;
    }

    float *sent, *scores, *keys, *qkv, *kv, *q4, *a4, *aO, *t0, *xec, *xcc, *obuf, *hid, *out2;
    int *vm, *tm, *ecm, *km;
    cudaGetSymbolAddress((void**)&sent,   g_sent);
    cudaGetSymbolAddress((void**)&scores, g_scores);
    cudaGetSymbolAddress((void**)&vm,     g_vm);
    cudaGetSymbolAddress((void**)&tm,     g_tm);
    cudaGetSymbolAddress((void**)&ecm,    g_ecm);
    cudaGetSymbolAddress((void**)&km,     g_km);
    cudaGetSymbolAddress((void**)&keys,   g_keys);
    cudaGetSymbolAddress((void**)&qkv,    g_qkv);
    cudaGetSymbolAddress((void**)&kv,     g_kv);
    cudaGetSymbolAddress((void**)&q4,     g_q4);
    cudaGetSymbolAddress((void**)&a4,     g_a4);
    cudaGetSymbolAddress((void**)&aO,     g_attnO);
    cudaGetSymbolAddress((void**)&t0,     g_t0);
    cudaGetSymbolAddress((void**)&xec,    g_xec);
    cudaGetSymbolAddress((void**)&xcc,    g_xcc);
    cudaGetSymbolAddress((void**)&obuf,   g_out);
    cudaGetSymbolAddress((void**)&hid,    g_hid);
    cudaGetSymbolAddress((void**)&out2,   g_out2);

    const float scale = 0.125f;   // 1/sqrt(64)
    const size_t TD = (size_t)TOK * CD;

    // ---- fork ----
    cudaEventRecord(evFork, 0);
    cudaStreamWaitEvent(s1, evFork, 0);
    cudaStreamWaitEvent(s2, evFork, 0);

    // ---- stream 0: vm + EC gemms/flash ----
    canon_mask<<<32, 256>>>(vmask, CB * CL, vm);
    cudaEventRecord(evVm, 0);
    gemm_tc<<<dim3(12, 64), 256>>>(x, 0, ec_in_w, 0, ec_in_b, 0, qkv, 0,
                                   TOK, 3 * CD, CD, 0, 0);

    // ---- stream s2: topk chain (overlaps with QKV gemm) ----
    canon_mask<<<1, 256, 0, s2>>>(tmask, CB * CLT, tm);
    sent_pool<<<CB, 256, 0, s2>>>(txt, tm, wts_w, wts_b, sent);
    cudaStreamWaitEvent(s2, evVm, 0);
    score_dot<<<1024, 256, 0, s2>>>(x, sent, vm, scores);
    rank_topk<<<CB, 1024, 0, s2>>>(scores, vm, ecm);
    cudaEventRecord(evTopk, s2);

    cudaStreamWaitEvent(0, evTopk, 0);
    flash_attn<<<dim3(8, 64, 1), 256, FA_SMEM>>>(qkv, 3 * CD, 0, 0, qkv, 3 * CD, CD, 2 * CD,
                                                 ecm, aO, 0, CL, scale, 0);
    gemm_tc<<<dim3(4, 64), 256>>>(aO, 0, ec_out_w, 0, ec_out_b, 0, t0, 0,
                                  TOK, CD, CD, 0, 0);
    ln_res<<<TOK, 256>>>(x, t0, ec_g, ec_b, xec);

    // ---- stream s1: CC branch ----
    gemm_tc<<<dim3(4, 64, 4), 256, 0, s1>>>(x, 0,
                                            cc_in_w, (size_t)3 * CD * CD,
                                            cc_in_b, (size_t)3 * CD,
                                            q4, TD, TOK, CD, CD, 0, 0);
    cudaStreamWaitEvent(s1, evVm, 0);
    pool_all<<<dim3(SUMLK, CB), 256, 0, s1>>>(x, vm, keys, km);
    gemm_tc<<<dim3(8, 96, 4), 256, 0, s1>>>(keys, 0,
        cc_in_w + (size_t)CD * CD, (size_t)3 * CD * CD,
        cc_in_b + CD, (size_t)3 * CD,
        kv, 0, 0, 2 * CD, CD, 0, 1);
    flash_attn<<<dim3(8, 64, 4), 256, FA_SMEM, s1>>>(q4, CD, 0, TD, kv, 2 * CD, 0, CD,
                                                     km, a4, TD, 0, scale, 1);
    gemm_tc<<<dim3(4, 64, 4), 256, 0, s1>>>(a4, TD,
                                            cc_out_w, (size_t)CD * CD,
                                            cc_out_b, (size_t)CD,
                                            hid, TD, TOK, CD, CD, 0, 0);
    ln_res4<<<TOK, 256, 0, s1>>>(x, hid, TD, cc_g, cc_b, xcc);
    cudaEventRecord(evB, s1);

    // ---- join + tail ----
    cudaStreamWaitEvent(0, evB, 0);
    add2<<<256, 256>>>(xec, xcc, obuf, TOK * CD);
    gemm_tc<<<dim3(16, 64), 256>>>(obuf, 0, lin1_w, 0, lin1_b, 0, hid, 0,
                                   TOK, 4 * CD, CD, 1, 0);
    gemm_tc<<<dim3(4, 64), 256>>>(hid, 0, lin2_w, 0, lin2_b, 0, out2, 0,
                                  TOK, CD, 4 * CD, 0, 0);
    ln_res<<<TOK, 256>>>(obuf, out2, fu_g, fu_b, out);
}

// round 17
// speedup vs baseline: 1.3592x; 1.2076x over previous
#include <cuda_runtime.h>
#include <cuda_fp16.h>
#include <math.h>

#define CL   1024
#define CB   8
#define CD   512
#define CH   8
#define CHD  64
#define CLT  32
#define TOK  (CL*CB)          // 8192
#define SUMLK 2081            // 1536+384+107+54
#define KEYTOK (SUMLK*CB)     // 16648

// ---------------- static scratch (allocation-free rule) ----------------
__device__ float g_sent[CB*CD];
__device__ float g_scores[CB*CL];
__device__ int   g_vm[CB*CL];
__device__ int   g_tm[CB*CLT];
__device__ int   g_ecm[CB*CL];
__device__ int   g_km[CB*SUMLK];
__device__ float g_keys[(size_t)KEYTOK*CD];
__device__ float g_qkv[(size_t)TOK*3*CD];      // EC QKV
__device__ float g_kv[(size_t)KEYTOK*2*CD];    // CC KV
__device__ float g_q4[(size_t)4*TOK*CD];
__device__ float g_a4[(size_t)4*TOK*CD];
__device__ float g_attnO[(size_t)TOK*CD];
__device__ float g_t0[(size_t)TOK*CD];
__device__ float g_xec[(size_t)TOK*CD];
__device__ float g_xcc[(size_t)TOK*CD];
__device__ float g_out[(size_t)TOK*CD];
__device__ float g_hid[(size_t)TOK*4*CD];
__device__ float g_out2[(size_t)TOK*CD];

__constant__ int cc_Lk[4]  = {1536, 384, 107, 54};
__constant__ int cc_Off[4] = {0, 12288, 15360, 16216};
// pooled-segment tables (8 pools flattened over 2081 positions)
__constant__ int pp_s[8]     = {1, 2, 4, 8, 16, 24, 32, 48};
__constant__ int pp_start[8] = {0, 1024, 1536, 1792, 1920, 1984, 2027, 2059};
__constant__ int pp_coff[8]  = {0, 1024, 0, 256, 0, 64, 0, 32};
__constant__ int pp_grp[8]   = {0, 0, 1, 1, 2, 2, 3, 3};

// ---------------- tf32 / fp16 helpers ----------------
__device__ __forceinline__ unsigned f2tf32(float x) {
    unsigned r; asm("cvt.rna.tf32.f32 %0, %1;" : "=r"(r) : "f"(x)); return r;
}
__device__ __forceinline__ void mma_tf32(float* d, const unsigned* a, const unsigned* b) {
    asm volatile(
        "mma.sync.aligned.m16n8k8.row.col.f32.tf32.tf32.f32 "
        "{%0,%1,%2,%3}, {%4,%5,%6,%7}, {%8,%9}, {%0,%1,%2,%3};\n"
        : "+f"(d[0]), "+f"(d[1]), "+f"(d[2]), "+f"(d[3])
        : "r"(a[0]), "r"(a[1]), "r"(a[2]), "r"(a[3]),
          "r"(b[0]), "r"(b[1]));
}
__device__ __forceinline__ unsigned f2h2(float lo, float hi) {
    __half2 h = __floats2half2_rn(lo, hi);
    return *(unsigned*)&h;
}
__device__ __forceinline__ void mma_fp16(float* d, const unsigned* a, const unsigned* b) {
    asm volatile(
        "mma.sync.aligned.m16n8k16.row.col.f32.f16.f16.f32 "
        "{%0,%1,%2,%3}, {%4,%5,%6,%7}, {%8,%9}, {%0,%1,%2,%3};\n"
        : "+f"(d[0]), "+f"(d[1]), "+f"(d[2]), "+f"(d[3])
        : "r"(a[0]), "r"(a[1]), "r"(a[2]), "r"(a[3]),
          "r"(b[0]), "r"(b[1]));
}

// ---------------- mask canonicalization ----------------
__global__ void canon_mask(const void* __restrict__ src, int n, int* __restrict__ dst) {
    unsigned int w = *(const unsigned int*)src;
    int mode = (w == 1u) ? 0 : (w == 0x01010101u) ? 1 : 2;
    for (int i = blockIdx.x * blockDim.x + threadIdx.x; i < n; i += gridDim.x * blockDim.x) {
        int v;
        if (mode == 0)      v = ((const int*)src)[i] != 0;
        else if (mode == 1) v = ((const unsigned char*)src)[i] != 0;
        else                v = ((const float*)src)[i] != 0.f;
        dst[i] = v;
    }
}

// ---------------- sentence-level text pooling ----------------
__global__ void sent_pool(const float* __restrict__ txt, const int* __restrict__ tm,
                          const float* __restrict__ wts_w, const float* __restrict__ wts_b,
                          float* __restrict__ sent) {
    int b = blockIdx.x;
    __shared__ float aw[CLT];
    int tid = threadIdx.x, wid = tid >> 5, lane = tid & 31;
    for (int t = wid; t < CLT; t += 8) {
        const float* row = txt + ((size_t)t * CB + b) * CD;
        float s = 0.f;
        for (int d = lane; d < CD; d += 32) s += row[d] * wts_w[d];
        #pragma unroll
        for (int o = 16; o; o >>= 1) s += __shfl_xor_sync(~0u, s, o);
        if (lane == 0) aw[t] = tm[b * CLT + t] ? s + wts_b[0] : -1e9f;
    }
    __syncthreads();
    if (tid == 0) {
        float mx = -3.4e38f;
        for (int t = 0; t < CLT; t++) mx = fmaxf(mx, aw[t]);
        float sm = 0.f;
        for (int t = 0; t < CLT; t++) { aw[t] = expf(aw[t] - mx); sm += aw[t]; }
        float inv = 1.f / sm;
        for (int t = 0; t < CLT; t++) aw[t] *= inv;
    }
    __syncthreads();
    for (int d = tid; d < CD; d += blockDim.x) {
        float s = 0.f;
        for (int t = 0; t < CLT; t++) s += aw[t] * txt[((size_t)t * CB + b) * CD + d];
        sent[b * CD + d] = s;
    }
}

// ---------------- relevance scores ----------------
__global__ void score_dot(const float* __restrict__ x, const float* __restrict__ sent,
                          const int* __restrict__ vm, float* __restrict__ scores) {
    int w = (blockIdx.x * blockDim.x + threadIdx.x) >> 5;
    int lane = threadIdx.x & 31;
    if (w >= CB * CL) return;
    int b = w & 7, l = w >> 3;
    const float4* xr = (const float4*)(x + ((size_t)(l * CB + b)) * CD);
    const float4* sb = (const float4*)(sent + b * CD);
    float acc = 0.f;
    for (int d = lane; d < CD / 4; d += 32) {
        float4 a = xr[d], c = sb[d];
        acc += a.x * c.x + a.y * c.y + a.z * c.z + a.w * c.w;
    }
    #pragma unroll
    for (int o = 16; o; o >>= 1) acc += __shfl_xor_sync(~0u, acc, o);
    if (lane == 0) {
        if (!vm[b * CL + l]) acc = -1e9f;
        scores[b * CL + l] = acc;
    }
}

// ---------------- exact rank top-k ----------------
__global__ void rank_topk(const float* __restrict__ scores, const int* __restrict__ vm,
                          int* __restrict__ ecm) {
    int b = blockIdx.x, l = threadIdx.x;
    __shared__ float s[CL];
    float mine = scores[b * CL + l];
    s[l] = mine;
    __syncthreads();
    int cnt = 0;
    for (int j = 0; j < CL; j++) {
        float sj = s[j];
        cnt += (sj > mine) || (sj == mine && j < l);
    }
    ecm[b * CL + l] = (cnt >= CL / 2) || !vm[b * CL + l];
}

// ======== fp16 TC GEMM (R8 structure, m16n8k16): static smem, reg-prefetch ========
// mode 0: C[z] = A[z](MxK) @ W[z](NxK)^T + bias[z], strides aZ/wZ/bZ/cZ.
// mode 1 (CC KV): per-z ragged M = cc_Lk[z]*CB, A/C offset by cc_Off[z] rows.
// smem holds packed half2 (k-pairs). fp32 accumulate.
__global__ void gemm_tc(const float* __restrict__ Ab, size_t aZ,
                        const float* __restrict__ Wb, size_t wZ,
                        const float* __restrict__ biasb, size_t bZ,
                        float* __restrict__ Cb, size_t cZ,
                        int M, int N, int K, int relu, int kvmode) {
    __shared__ unsigned As[128][20];   // 16 half2 (=32 k) used, pad 20 (conflict-free)
    __shared__ unsigned Ws[128][20];
    int z = blockIdx.z;
    const float* A;
    const float* W = Wb + (size_t)z * wZ;
    const float* bias = biasb + (size_t)z * bZ;
    float* C;
    if (kvmode) {
        M = cc_Lk[z] * CB;
        A = Ab + (size_t)cc_Off[z] * CD;
        C = Cb + (size_t)cc_Off[z] * 2 * CD;
    } else {
        A = Ab + (size_t)z * aZ;
        C = Cb + (size_t)z * cZ;
    }

    int row0 = blockIdx.y << 7, col0 = blockIdx.x << 7;
    if (row0 >= M) return;

    int tid = threadIdx.x;
    int wid = tid >> 5, lane = tid & 31;
    int g = lane >> 2, tg = lane & 3;
    int wm = wid >> 2, wn = wid & 3;
    int mb = wm * 64, nb = wn * 32;
    float acc[4][4][4] = {};
    float4 pa[4], pw[4];

    // prefetch chunk 0
    #pragma unroll
    for (int v = 0; v < 4; v++) {
        int idx = tid + v * 256;
        int r = idx >> 3, c4 = idx & 7;
        int gm = row0 + r;
        pa[v] = (gm < M) ? *(const float4*)&A[(size_t)gm * K + c4 * 4]
                         : make_float4(0.f, 0.f, 0.f, 0.f);
        pw[v] = *(const float4*)&W[(size_t)(col0 + r) * K + c4 * 4];
    }

    for (int k0 = 0; k0 < K; k0 += 32) {
        // commit prefetched chunk to smem as packed half2
        #pragma unroll
        for (int v = 0; v < 4; v++) {
            int idx = tid + v * 256;
            int r = idx >> 3, c4 = idx & 7;
            As[r][c4 * 2 + 0] = f2h2(pa[v].x, pa[v].y);
            As[r][c4 * 2 + 1] = f2h2(pa[v].z, pa[v].w);
            Ws[r][c4 * 2 + 0] = f2h2(pw[v].x, pw[v].y);
            Ws[r][c4 * 2 + 1] = f2h2(pw[v].z, pw[v].w);
        }
        __syncthreads();
        if (k0 + 32 < K) {
            int kn = k0 + 32;
            #pragma unroll
            for (int v = 0; v < 4; v++) {
                int idx = tid + v * 256;
                int r = idx >> 3, c4 = idx & 7;
                int gm = row0 + r;
                pa[v] = (gm < M) ? *(const float4*)&A[(size_t)gm * K + kn + c4 * 4]
                                 : make_float4(0.f, 0.f, 0.f, 0.f);
                pw[v] = *(const float4*)&W[(size_t)(col0 + r) * K + kn + c4 * 4];
            }
        }
        // mainloop: 2 k-steps of 16 (vs 4 steps of 8 in tf32) — half the MMAs
        #pragma unroll
        for (int ks = 0; ks < 2; ks++) {
            int kh = ks * 8;   // half2 index base (8 half2 = 16 k)
            unsigned af[4][4], bf[4][2];
            #pragma unroll
            for (int i = 0; i < 4; i++) {
                int m = mb + i * 16;
                af[i][0] = As[m + g][kh + tg];
                af[i][1] = As[m + g + 8][kh + tg];
                af[i][2] = As[m + g][kh + tg + 4];
                af[i][3] = As[m + g + 8][kh + tg + 4];
            }
            #pragma unroll
            for (int j = 0; j < 4; j++) {
                int n = nb + j * 8;
                bf[j][0] = Ws[n + g][kh + tg];
                bf[j][1] = Ws[n + g][kh + tg + 4];
            }
            #pragma unroll
            for (int i = 0; i < 4; i++)
                #pragma unroll
                for (int j = 0; j < 4; j++) mma_fp16(acc[i][j], af[i], bf[j]);
        }
        __syncthreads();
    }
    #pragma unroll
    for (int i = 0; i < 4; i++) {
        #pragma unroll
        for (int j = 0; j < 4; j++) {
            int gn = col0 + nb + j * 8 + tg * 2;
            float b0 = bias[gn], b1 = bias[gn + 1];
            #pragma unroll
            for (int h = 0; h < 2; h++) {
                int gm = row0 + mb + i * 16 + g + h * 8;
                if (gm >= M) continue;
                float c0 = acc[i][j][h * 2 + 0] + b0;
                float c1 = acc[i][j][h * 2 + 1] + b1;
                if (relu) { c0 = fmaxf(c0, 0.f); c1 = fmaxf(c1, 0.f); }
                *(float2*)&C[(size_t)gm * N + gn] = make_float2(c0, c1);
            }
        }
    }
}

// ================= fused flash attention (tf32, unchanged) =================
#define FA_QS   0
#define FA_KS   (128*68)
#define FA_VS   (FA_KS + 64*68)
#define FA_PS   (FA_VS + 64*68)
#define FA_KM   (FA_PS + 8*16*68)
#define FA_SMEM ((FA_KM + 64) * 4)

__global__ void __launch_bounds__(256, 2)
flash_attn(const float* __restrict__ Qb, int sQ, int qoff, size_t qZ,
           const float* __restrict__ KVb, int sKV, int koff, int voff,
           const int* __restrict__ ignb, float* __restrict__ Ob, size_t oZ,
           int Lk0, float scale, int multi) {
    extern __shared__ unsigned sm[];
    unsigned* Qs = sm + FA_QS;
    unsigned* Ks = sm + FA_KS;
    unsigned* Vs = sm + FA_VS;
    unsigned* Ps = sm + FA_PS;
    int* kms = (int*)(sm + FA_KM);

    int z = blockIdx.z;
    int Lk = Lk0, rowoff = 0;
    const float* Q = Qb;
    const int* ign = ignb;
    float* O = Ob;
    if (multi) {
        Lk = cc_Lk[z];
        rowoff = cc_Off[z];
        Q = Qb + (size_t)z * qZ;
        O = Ob + (size_t)z * oZ;
        ign = ignb + rowoff;
    }

    int bh = blockIdx.y, b = bh >> 3, h = bh & 7;
    int lq0 = blockIdx.x << 7;
    int tid = threadIdx.x, wid = tid >> 5, lane = tid & 31;
    int g = lane >> 2, tg = lane & 3;
    unsigned* wp = Ps + wid * (16 * 68);
    int mb = wid * 16;

    #pragma unroll
    for (int v = 0; v < 8; v++) {
        int idx = tid + v * 256;
        int r = idx >> 4, c4 = idx & 15;
        float4 q = *(const float4*)&Q[((size_t)((lq0 + r) * CB + b)) * sQ + qoff + h * CHD + c4 * 4];
        Qs[r * 68 + c4 * 4 + 0] = f2tf32(q.x);
        Qs[r * 68 + c4 * 4 + 1] = f2tf32(q.y);
        Qs[r * 68 + c4 * 4 + 2] = f2tf32(q.z);
        Qs[r * 68 + c4 * 4 + 3] = f2tf32(q.w);
    }

    float o[8][4] = {};
    float mA = -1e30f, mB = -1e30f, lA = 0.f, lB = 0.f;

    for (int kt = 0; kt < Lk; kt += 64) {
        __syncthreads();
        #pragma unroll
        for (int v = 0; v < 4; v++) {
            int idx = tid + v * 256;
            int r = idx >> 4, c4 = idx & 15;
            int key = kt + r;
            float4 kv = make_float4(0.f, 0.f, 0.f, 0.f);
            float4 vv = make_float4(0.f, 0.f, 0.f, 0.f);
            if (key < Lk) {
                size_t base = ((size_t)(rowoff + key * CB + b)) * sKV;
                kv = *(const float4*)&KVb[base + koff + h * CHD + c4 * 4];
                vv = *(const float4*)&KVb[base + voff + h * CHD + c4 * 4];
            }
            Ks[r * 68 + c4 * 4 + 0] = f2tf32(kv.x);
            Ks[r * 68 + c4 * 4 + 1] = f2tf32(kv.y);
            Ks[r * 68 + c4 * 4 + 2] = f2tf32(kv.z);
            Ks[r * 68 + c4 * 4 + 3] = f2tf32(kv.w);
            Vs[r * 68 + c4 * 4 + 0] = f2tf32(vv.x);
            Vs[r * 68 + c4 * 4 + 1] = f2tf32(vv.y);
            Vs[r * 68 + c4 * 4 + 2] = f2tf32(vv.z);
            Vs[r * 68 + c4 * 4 + 3] = f2tf32(vv.w);
        }
        if (tid < 64) {
            int key = kt + tid;
            kms[tid] = (key < Lk) ? ign[b * Lk + key] : 1;
        }
        __syncthreads();

        float s[8][4] = {};
        #pragma unroll
        for (int kk = 0; kk < 64; kk += 8) {
            unsigned a[4];
            a[0] = Qs[(mb + g) * 68 + kk + tg];
            a[1] = Qs[(mb + g + 8) * 68 + kk + tg];
            a[2] = Qs[(mb + g) * 68 + kk + tg + 4];
            a[3] = Qs[(mb + g + 8) * 68 + kk + tg + 4];
            #pragma unroll
            for (int j = 0; j < 8; j++) {
                unsigned bfr[2];
                bfr[0] = Ks[(j * 8 + g) * 68 + kk + tg];
                bfr[1] = Ks[(j * 8 + g) * 68 + kk + tg + 4];
                mma_tf32(s[j], a, bfr);
            }
        }
        #pragma unroll
        for (int j = 0; j < 8; j++) {
            int c0 = j * 8 + tg * 2;
            int m0 = kms[c0], m1 = kms[c0 + 1];
            s[j][0] = m0 ? -1e30f : s[j][0] * scale;
            s[j][1] = m1 ? -1e30f : s[j][1] * scale;
            s[j][2] = m0 ? -1e30f : s[j][2] * scale;
            s[j][3] = m1 ? -1e30f : s[j][3] * scale;
        }
        float tA = -3.4e38f, tB = -3.4e38f;
        #pragma unroll
        for (int j = 0; j < 8; j++) {
            tA = fmaxf(tA, fmaxf(s[j][0], s[j][1]));
            tB = fmaxf(tB, fmaxf(s[j][2], s[j][3]));
        }
        #pragma unroll
        for (int off = 1; off <= 2; off <<= 1) {
            tA = fmaxf(tA, __shfl_xor_sync(~0u, tA, off));
            tB = fmaxf(tB, __shfl_xor_sync(~0u, tB, off));
        }
        float mnA = fmaxf(mA, tA), mnB = fmaxf(mB, tB);
        float aA = __expf(mA - mnA), aB = __expf(mB - mnB);
        float suA = 0.f, suB = 0.f;
        #pragma unroll
        for (int j = 0; j < 8; j++) {
            s[j][0] = __expf(s[j][0] - mnA);
            s[j][1] = __expf(s[j][1] - mnA);
            s[j][2] = __expf(s[j][2] - mnB);
            s[j][3] = __expf(s[j][3] - mnB);
            suA += s[j][0] + s[j][1];
            suB += s[j][2] + s[j][3];
        }
        #pragma unroll
        for (int off = 1; off <= 2; off <<= 1) {
            suA += __shfl_xor_sync(~0u, suA, off);
            suB += __shfl_xor_sync(~0u, suB, off);
        }
        lA = lA * aA + suA;  mA = mnA;
        lB = lB * aB + suB;  mB = mnB;
        #pragma unroll
        for (int j = 0; j < 8; j++) {
            o[j][0] *= aA; o[j][1] *= aA;
            o[j][2] *= aB; o[j][3] *= aB;
        }
        #pragma unroll
        for (int j = 0; j < 8; j++) {
            int c0 = j * 8 + tg * 2;
            wp[g * 68 + c0]           = f2tf32(s[j][0]);
            wp[g * 68 + c0 + 1]       = f2tf32(s[j][1]);
            wp[(g + 8) * 68 + c0]     = f2tf32(s[j][2]);
            wp[(g + 8) * 68 + c0 + 1] = f2tf32(s[j][3]);
        }
        __syncwarp();
        #pragma unroll
        for (int kk = 0; kk < 64; kk += 8) {
            unsigned a[4];
            a[0] = wp[g * 68 + kk + tg];
            a[1] = wp[(g + 8) * 68 + kk + tg];
            a[2] = wp[g * 68 + kk + tg + 4];
            a[3] = wp[(g + 8) * 68 + kk + tg + 4];
            #pragma unroll
            for (int j = 0; j < 8; j++) {
                unsigned bfr[2];
                bfr[0] = Vs[(kk + tg) * 68 + j * 8 + g];
                bfr[1] = Vs[(kk + tg + 4) * 68 + j * 8 + g];
                mma_tf32(o[j], a, bfr);
            }
        }
        __syncwarp();
    }
    float iA = 1.f / lA, iB = 1.f / lB;
    int lqA = lq0 + mb + g, lqB = lqA + 8;
    #pragma unroll
    for (int j = 0; j < 8; j++) {
        int c = h * CHD + j * 8 + tg * 2;
        *(float2*)&O[((size_t)(lqA * CB + b)) * CD + c] = make_float2(o[j][0] * iA, o[j][1] * iA);
        *(float2*)&O[((size_t)(lqB * CB + b)) * CD + c] = make_float2(o[j][2] * iB, o[j][3] * iB);
    }
}

// ---------------- all pools in one launch (flattened 2081 positions) ----------------
__global__ void pool_all(const float* __restrict__ x, const int* __restrict__ vm,
                         float* __restrict__ keys, int* __restrict__ kmask) {
    int q = blockIdx.x, b = blockIdx.y;
    int tid = threadIdx.x;
    int p = 7;
    #pragma unroll
    for (int i = 7; i >= 1; i--) if (q < pp_start[i]) p = i - 1;
    int lp = q - pp_start[p];
    int s = pp_s[p];
    int gidx = pp_grp[p];
    int orowIdx = cc_Off[gidx] + (pp_coff[p] + lp) * CB + b;
    size_t orow = (size_t)orowIdx * CD;
    for (int d = tid; d < CD; d += 256) {
        float m = -3.4e38f;
        for (int j = 0; j < s; j++) {
            int l = lp * s + j;
            float v = (l < CL) ? x[((size_t)l * CB + b) * CD + d] : 0.f;
            m = fmaxf(m, v);
        }
        keys[orow + d] = m;
    }
    if (tid == 0) {
        int any = 0;
        for (int j = 0; j < s; j++) {
            int l = lp * s + j;
            if (l < CL && vm[b * CL + l]) any = 1;
        }
        int Lkg = cc_Lk[gidx];
        kmask[cc_Off[gidx] + b * Lkg + (pp_coff[p] + lp)] = !any;
    }
}

// ---------------- LayerNorm(A + R) ----------------
__global__ void ln_res(const float* __restrict__ A, const float* __restrict__ R,
                       const float* __restrict__ g, const float* __restrict__ be,
                       float* __restrict__ out) {
    size_t row = blockIdx.x;
    int tid = threadIdx.x;
    __shared__ float red[256];
    float v0 = A[row * CD + tid]       + R[row * CD + tid];
    float v1 = A[row * CD + tid + 256] + R[row * CD + tid + 256];
    red[tid] = v0 + v1; __syncthreads();
    for (int s = 128; s > 0; s >>= 1) { if (tid < s) red[tid] += red[tid + s]; __syncthreads(); }
    float mu = red[0] / CD; __syncthreads();
    float d0 = v0 - mu, d1 = v1 - mu;
    red[tid] = d0 * d0 + d1 * d1; __syncthreads();
    for (int s = 128; s > 0; s >>= 1) { if (tid < s) red[tid] += red[tid + s]; __syncthreads(); }
    float rstd = rsqrtf(red[0] / CD + 1e-5f);
    out[row * CD + tid]       = d0 * rstd * g[tid]       + be[tid];
    out[row * CD + tid + 256] = d1 * rstd * g[tid + 256] + be[tid + 256];
}

// ---------------- LayerNorm(x + P0+P1+P2+P3) ----------------
__global__ void ln_res4(const float* __restrict__ X, const float* __restrict__ P, size_t pZ,
                        const float* __restrict__ g, const float* __restrict__ be,
                        float* __restrict__ out) {
    size_t row = blockIdx.x;
    int tid = threadIdx.x;
    __shared__ float red[256];
    size_t i0 = row * CD + tid, i1 = i0 + 256;
    float v0 = X[i0] + P[i0] + P[i0 + pZ] + P[i0 + 2 * pZ] + P[i0 + 3 * pZ];
    float v1 = X[i1] + P[i1] + P[i1 + pZ] + P[i1 + 2 * pZ] + P[i1 + 3 * pZ];
    red[tid] = v0 + v1; __syncthreads();
    for (int s = 128; s > 0; s >>= 1) { if (tid < s) red[tid] += red[tid + s]; __syncthreads(); }
    float mu = red[0] / CD; __syncthreads();
    float d0 = v0 - mu, d1 = v1 - mu;
    red[tid] = d0 * d0 + d1 * d1; __syncthreads();
    for (int s = 128; s > 0; s >>= 1) { if (tid < s) red[tid] += red[tid + s]; __syncthreads(); }
    float rstd = rsqrtf(red[0] / CD + 1e-5f);
    out[i0] = d0 * rstd * g[tid]       + be[tid];
    out[i1] = d1 * rstd * g[tid + 256] + be[tid + 256];
}

__global__ void add2(const float* __restrict__ a, const float* __restrict__ b,
                     float* __restrict__ c, int n) {
    for (int i = blockIdx.x * blockDim.x + threadIdx.x; i < n; i += gridDim.x * blockDim.x)
        c[i] = a[i] + b[i];
}

// ---------------- launch ----------------
static inline int cdiv(int a, int b) { return (a + b - 1) / b; }

extern "C" void kernel_launch(void* const* d_in, const int* in_sizes, int n_in,
                              void* d_out, int out_size) {
    const float* x        = (const float*)d_in[0];
    const float* txt      = (const float*)d_in[1];
    const void*  vmask    = d_in[2];
    const void*  tmask    = d_in[3];
    const float* wts_w    = (const float*)d_in[4];
    const float* wts_b    = (const float*)d_in[5];
    const float* ec_in_w  = (const float*)d_in[6];
    const float* ec_in_b  = (const float*)d_in[7];
    const float* ec_out_w = (const float*)d_in[8];
    const float* ec_out_b = (const float*)d_in[9];
    const float* cc_in_w  = (const float*)d_in[10];
    const float* cc_in_b  = (const float*)d_in[11];
    const float* cc_out_w = (const float*)d_in[12];
    const float* cc_out_b = (const float*)d_in[13];
    const float* ec_g     = (const float*)d_in[14];
    const float* ec_b     = (const float*)d_in[15];
    const float* cc_g     = (const float*)d_in[16];
    const float* cc_b     = (const float*)d_in[17];
    const float* fu_g     = (const float*)d_in[18];
    const float* fu_b     = (const float*)d_in[19];
    const float* lin1_w   = (const float*)d_in[20];
    const float* lin1_b   = (const float*)d_in[21];
    const float* lin2_w   = (const float*)d_in[22];
    const float* lin2_b   = (const float*)d_in[23];
    float* out = (float*)d_out;

    static int init_done = 0;
    static cudaStream_t s1, s2;
    static cudaEvent_t evFork, evVm, evB, evTopk;
    if (!init_done) {
        cudaFuncSetAttribute(flash_attn, cudaFuncAttributeMaxDynamicSharedMemorySize, FA_SMEM);
        cudaStreamCreateWithFlags(&s1, cudaStreamNonBlocking);
        cudaStreamCreateWithFlags(&s2, cudaStreamNonBlocking);
        cudaEventCreateWithFlags(&evFork, cudaEventDisableTiming);
        cudaEventCreateWithFlags(&evVm,   cudaEventDisableTiming);
        cudaEventCreateWithFlags(&evB,    cudaEventDisableTiming);
        cudaEventCreateWithFlags(&evTopk, cudaEventDisableTiming);
        init_done = 1;
    }

    float *sent, *scores, *keys, *qkv, *kv, *q4, *a4, *aO, *t0, *xec, *xcc, *obuf, *hid, *out2;
    int *vm, *tm, *ecm, *km;
    cudaGetSymbolAddress((void**)&sent,   g_sent);
    cudaGetSymbolAddress((void**)&scores, g_scores);
    cudaGetSymbolAddress((void**)&vm,     g_vm);
    cudaGetSymbolAddress((void**)&tm,     g_tm);
    cudaGetSymbolAddress((void**)&ecm,    g_ecm);
    cudaGetSymbolAddress((void**)&km,     g_km);
    cudaGetSymbolAddress((void**)&keys,   g_keys);
    cudaGetSymbolAddress((void**)&qkv,    g_qkv);
    cudaGetSymbolAddress((void**)&kv,     g_kv);
    cudaGetSymbolAddress((void**)&q4,     g_q4);
    cudaGetSymbolAddress((void**)&a4,     g_a4);
    cudaGetSymbolAddress((void**)&aO,     g_attnO);
    cudaGetSymbolAddress((void**)&t0,     g_t0);
    cudaGetSymbolAddress((void**)&xec,    g_xec);
    cudaGetSymbolAddress((void**)&xcc,    g_xcc);
    cudaGetSymbolAddress((void**)&obuf,   g_out);
    cudaGetSymbolAddress((void**)&hid,    g_hid);
    cudaGetSymbolAddress((void**)&out2,   g_out2);

    const float scale = 0.125f;   // 1/sqrt(64)
    const size_t TD = (size_t)TOK * CD;

    // ---- fork ----
    cudaEventRecord(evFork, 0);
    cudaStreamWaitEvent(s1, evFork, 0);
    cudaStreamWaitEvent(s2, evFork, 0);

    // ---- stream 0: vm + EC gemms/flash ----
    canon_mask<<<32, 256>>>(vmask, CB * CL, vm);
    cudaEventRecord(evVm, 0);
    gemm_tc<<<dim3(12, 64), 256>>>(x, 0, ec_in_w, 0, ec_in_b, 0, qkv, 0,
                                   TOK, 3 * CD, CD, 0, 0);

    // ---- stream s2: topk chain (overlaps with QKV gemm) ----
    canon_mask<<<1, 256, 0, s2>>>(tmask, CB * CLT, tm);
    sent_pool<<<CB, 256, 0, s2>>>(txt, tm, wts_w, wts_b, sent);
    cudaStreamWaitEvent(s2, evVm, 0);
    score_dot<<<1024, 256, 0, s2>>>(x, sent, vm, scores);
    rank_topk<<<CB, 1024, 0, s2>>>(scores, vm, ecm);
    cudaEventRecord(evTopk, s2);

    cudaStreamWaitEvent(0, evTopk, 0);
    flash_attn<<<dim3(8, 64, 1), 256, FA_SMEM>>>(qkv, 3 * CD, 0, 0, qkv, 3 * CD, CD, 2 * CD,
                                                 ecm, aO, 0, CL, scale, 0);
    gemm_tc<<<dim3(4, 64), 256>>>(aO, 0, ec_out_w, 0, ec_out_b, 0, t0, 0,
                                  TOK, CD, CD, 0, 0);
    ln_res<<<TOK, 256>>>(x, t0, ec_g, ec_b, xec);

    // ---- stream s1: CC branch ----
    gemm_tc<<<dim3(4, 64, 4), 256, 0, s1>>>(x, 0,
                                            cc_in_w, (size_t)3 * CD * CD,
                                            cc_in_b, (size_t)3 * CD,
                                            q4, TD, TOK, CD, CD, 0, 0);
    cudaStreamWaitEvent(s1, evVm, 0);
    pool_all<<<dim3(SUMLK, CB), 256, 0, s1>>>(x, vm, keys, km);
    gemm_tc<<<dim3(8, 96, 4), 256, 0, s1>>>(keys, 0,
        cc_in_w + (size_t)CD * CD, (size_t)3 * CD * CD,
        cc_in_b + CD, (size_t)3 * CD,
        kv, 0, 0, 2 * CD, CD, 0, 1);
    flash_attn<<<dim3(8, 64, 4), 256, FA_SMEM, s1>>>(q4, CD, 0, TD, kv, 2 * CD, 0, CD,
                                                     km, a4, TD, 0, scale, 1);
    gemm_tc<<<dim3(4, 64, 4), 256, 0, s1>>>(a4, TD,
                                            cc_out_w, (size_t)CD * CD,
                                            cc_out_b, (size_t)CD,
                                            hid, TD, TOK, CD, CD, 0, 0);
    ln_res4<<<TOK, 256, 0, s1>>>(x, hid, TD, cc_g, cc_b, xcc);
    cudaEventRecord(evB, s1);

    // ---- join + tail ----
    cudaStreamWaitEvent(0, evB, 0);
    add2<<<256, 256>>>(xec, xcc, obuf, TOK * CD);
    gemm_tc<<<dim3(16, 64), 256>>>(obuf, 0, lin1_w, 0, lin1_b, 0, hid, 0,
                                   TOK, 4 * CD, CD, 1, 0);
    gemm_tc<<<dim3(4, 64), 256>>>(hid, 0, lin2_w, 0, lin2_b, 0, out2, 0,
                                  TOK, CD, 4 * CD, 0, 0);
    ln_res<<<TOK, 256>>>(obuf, out2, fu_g, fu_b, out);
}